// round 2
// baseline (speedup 1.0000x reference)
#include <cuda_runtime.h>
#include <math.h>

#define Bsz 8
#define Lseq 2048
#define INF 64
#define OUTF 64
#define Hd 128
#define Nst 64
#define NLAY 4
#define L2 4096
#define ROWS (Bsz*Lseq)

// ---------------- persistent scratch (static device arrays; no allocation) ----------------
__device__ float  g_h [ROWS*Hd];     // current activations (B,L,H)
__device__ float  g_hn[ROWS*Hd];     // layernormed
__device__ float  g_y [ROWS*Hd];     // conv output (pre-gelu)
__device__ float2 g_at[Hd*Lseq];     // at_roots (H, L) complex
__device__ float2 g_Kd[Hd*L2];       // kernel spectrum (H, 4096) complex
__device__ float2 g_tw[L2/2];        // twiddles exp(-2*pi*i*m/4096), m < 2048

__device__ __forceinline__ float2 cmulf(float2 a, float2 b) {
    return make_float2(a.x*b.x - a.y*b.y, a.x*b.y + a.y*b.x);
}

// ---------------- twiddle table ----------------
__global__ void twiddle_kernel() {
    int m = blockIdx.x * blockDim.x + threadIdx.x;
    if (m < L2/2) {
        float s, c;
        sincospif(-(float)m / 2048.0f, &s, &c);
        g_tw[m] = make_float2(c, s);
    }
}

// ---------------- encoder: h = x @ enc_w.T + enc_b ----------------
__global__ void encoder_kernel(const float* __restrict__ x,
                               const float* __restrict__ w,
                               const float* __restrict__ bias) {
    const int R = 16;
    __shared__ float xs[R][INF];
    int row0 = blockIdx.x * R;
    int c = threadIdx.x;  // 128 threads = output channel
    for (int idx = c; idx < R*INF; idx += 128)
        xs[idx / INF][idx % INF] = x[(row0 + idx/INF)*INF + (idx % INF)];
    __syncthreads();
    float acc[R];
    float bv = bias[c];
    #pragma unroll
    for (int r = 0; r < R; r++) acc[r] = bv;
    for (int k = 0; k < INF; k++) {
        float wv = w[c*INF + k];
        #pragma unroll
        for (int r = 0; r < R; r++) acc[r] = fmaf(xs[r][k], wv, acc[r]);
    }
    #pragma unroll
    for (int r = 0; r < R; r++) g_h[(row0+r)*Hd + c] = acc[r];
}

// ---------------- layernorm over H ----------------
__global__ void ln_kernel(const float* __restrict__ nw, const float* __restrict__ nb) {
    int warp = (blockIdx.x * blockDim.x + threadIdx.x) >> 5;
    int lane = threadIdx.x & 31;
    if (warp >= ROWS) return;
    const float* row = g_h + (size_t)warp * Hd;
    float v[4];
    float sum = 0.f;
    #pragma unroll
    for (int i = 0; i < 4; i++) { v[i] = row[lane + 32*i]; sum += v[i]; }
    #pragma unroll
    for (int o = 16; o; o >>= 1) sum += __shfl_xor_sync(0xffffffffu, sum, o);
    float mu = sum * (1.0f/Hd);
    float var = 0.f;
    #pragma unroll
    for (int i = 0; i < 4; i++) { float t = v[i]-mu; var += t*t; }
    #pragma unroll
    for (int o = 16; o; o >>= 1) var += __shfl_xor_sync(0xffffffffu, var, o);
    var *= (1.0f/Hd);
    float rstd = rsqrtf(var + 1e-5f);
    float* outr = g_hn + (size_t)warp * Hd;
    #pragma unroll
    for (int i = 0; i < 4; i++) {
        int c = lane + 32*i;
        outr[c] = (v[i]-mu)*rstd*nw[c] + nb[c];
    }
}

// ---------------- cauchy / woodbury: at_roots (H, L) ----------------
__global__ void cauchy_kernel(const float* __restrict__ lre, const float* __restrict__ lim,
                              const float* __restrict__ pre, const float* __restrict__ pim,
                              const float* __restrict__ bre, const float* __restrict__ bim,
                              const float* __restrict__ cre, const float* __restrict__ cim,
                              const float* __restrict__ lstep) {
    int h = blockIdx.x;
    __shared__ float2 slam[Nst], s00[Nst], s01[Nst], s10[Nst], s11[Nst];
    int tid = threadIdx.x;
    if (tid < Nst) {
        int idx = h*Nst + tid;
        slam[tid] = make_float2(lre[idx], lim[idx]);
        float2 P  = make_float2(pre[idx], pim[idx]);
        float2 Bv = make_float2(bre[idx], bim[idx]);
        float2 Cc = make_float2(cre[idx], -cim[idx]);  // conj(C)
        float2 Pc = make_float2(P.x, -P.y);            // conj(P)
        s00[tid] = cmulf(Cc, Bv);
        s01[tid] = cmulf(Cc, P);
        s10[tid] = cmulf(Pc, Bv);
        s11[tid] = cmulf(Pc, P);
    }
    __syncthreads();
    float ts = 2.0f / __expf(lstep[h]);   // 2/step
    for (int l = tid; l < Lseq; l += blockDim.x) {
        // omega = exp(-2*pi*i*l/L), computed like XLA (f32 angle + sincosf).
        // Do NOT use sincospif here: at l=L/2 exact zero would produce NaN;
        // the f32-rounded angle gives a tiny nonzero imag that cancels analytically.
        float ang = -6.2831853071795864f * ((float)l / (float)Lseq);
        float s, c;
        sincosf(ang, &s, &c);
        float dpx = 1.0f + c, dpy = s;      // 1+omega
        float dmx = 1.0f - c, dmy = -s;     // 1-omega
        float id2 = __fdividef(1.0f, dpx*dpx + dpy*dpy);
        float gx = ts * (dmx*dpx + dmy*dpy) * id2;
        float gy = ts * (dmy*dpx - dmx*dpy) * id2;
        float c2x = 2.0f*dpx*id2, c2y = -2.0f*dpy*id2;  // c = 2/(1+omega)
        float k00x=0,k00y=0,k01x=0,k01y=0,k10x=0,k10y=0,k11x=0,k11y=0;
        #pragma unroll 8
        for (int n = 0; n < Nst; n++) {
            float dx = gx - slam[n].x;
            float dy = gy - slam[n].y;
            float inv = __fdividef(1.0f, dx*dx + dy*dy);
            float rx = dx*inv, ry = -dy*inv;  // 1/(g - lam)
            float2 v;
            v = s00[n]; k00x += v.x*rx - v.y*ry; k00y += v.x*ry + v.y*rx;
            v = s01[n]; k01x += v.x*rx - v.y*ry; k01y += v.x*ry + v.y*rx;
            v = s10[n]; k10x += v.x*rx - v.y*ry; k10y += v.x*ry + v.y*rx;
            v = s11[n]; k11x += v.x*rx - v.y*ry; k11y += v.x*ry + v.y*rx;
        }
        // woodbury: at = c * (k00 - k01 * k10 / (1 + k11))
        float opx = 1.0f + k11x, opy = k11y;
        float oinv = __fdividef(1.0f, opx*opx + opy*opy);
        float wx = k01x*k10x - k01y*k10y;
        float wy = k01x*k10y + k01y*k10x;
        float cx = (wx*opx + wy*opy) * oinv;
        float cy = (wy*opx - wx*opy) * oinv;
        float rx = k00x - cx, ry = k00y - cy;
        g_at[h*Lseq + l] = make_float2(c2x*rx - c2y*ry, c2x*ry + c2y*rx);
    }
}

// ---------------- in-smem Stockham radix-2 FFT ----------------
// Returns pointer to buffer holding the result (a if logn even, b if odd).
__device__ float2* block_fft(float2* a, float2* b, int n, int logn, bool inverse) {
    float2* src = a; float2* dst = b;
    int half = n >> 1;
    for (int t = 0; t < logn; t++) {
        __syncthreads();
        int Ls = 1 << t;
        int shift = 11 - t;  // twiddle table has 2048 entries for 4096-root
        for (int j = threadIdx.x; j < half; j += blockDim.x) {
            int k = j & (Ls - 1);
            int blk = j >> t;
            float2 u = src[j];
            float2 v = src[j + half];
            float2 w = g_tw[k << shift];
            float wy = inverse ? -w.y : w.y;
            float twx = w.x*v.x - wy*v.y;
            float twy = w.x*v.y + wy*v.x;
            int o = (blk << (t+1)) + k;
            dst[o]      = make_float2(u.x + twx, u.y + twy);
            dst[o + Ls] = make_float2(u.x - twx, u.y - twy);
        }
        float2* tmp = src; src = dst; dst = tmp;
    }
    __syncthreads();
    return src;
}

// ---------------- K = ifft(at_roots).real ; Kd = fft(K, 4096) ----------------
__global__ void kfft_kernel() {
    extern __shared__ float2 smemf[];
    float2* A  = smemf;
    float2* Bb = smemf + L2;
    int h = blockIdx.x;
    int tid = threadIdx.x;
    for (int l = tid; l < Lseq; l += blockDim.x) A[l] = g_at[h*Lseq + l];
    float2* r1 = block_fft(A, Bb, Lseq, 11, true);   // inverse 2048 -> ends in Bb
    for (int l = tid; l < L2; l += blockDim.x) {
        float kv = (l < Lseq) ? r1[l].x * (1.0f/Lseq) : 0.0f;
        A[l] = make_float2(kv, 0.0f);
    }
    float2* r2 = block_fft(A, Bb, L2, 12, false);    // forward 4096 -> ends in A
    for (int f = tid; f < L2; f += blockDim.x) g_Kd[h*L2 + f] = r2[f];
}

// ---------------- FFT causal conv: y = irfft(fft(hn) * Kd) + hn*d ----------------
__global__ void conv_kernel(const float* __restrict__ dvec) {
    extern __shared__ float2 smemf[];
    float2* A  = smemf;
    float2* Bb = smemf + L2;
    int bh = blockIdx.x;
    int b = bh / Hd, h = bh % Hd;
    int tid = threadIdx.x;
    const float* u = g_hn + (size_t)b*Lseq*Hd + h;   // stride Hd
    for (int l = tid; l < L2; l += blockDim.x) {
        float uv = (l < Lseq) ? u[(size_t)l*Hd] : 0.0f;
        A[l] = make_float2(uv, 0.0f);
    }
    float2* F = block_fft(A, Bb, L2, 12, false);     // in A
    const float2* kd = g_Kd + h*L2;
    for (int f = tid; f < L2; f += blockDim.x)
        F[f] = cmulf(F[f], kd[f]);
    float2* R = block_fft(A, Bb, L2, 12, true);      // in A
    float dv = dvec[h];
    float* yout = g_y + (size_t)b*Lseq*Hd + h;
    for (int l = tid; l < Lseq; l += blockDim.x)
        yout[(size_t)l*Hd] = R[l].x * (1.0f/L2) + u[(size_t)l*Hd] * dv;
}

// ---------------- gelu + gated MLP + residual ----------------
__global__ void mlp_kernel(const float* __restrict__ w1, const float* __restrict__ b1,
                           const float* __restrict__ w2, const float* __restrict__ b2) {
    const int R = 16;
    __shared__ float zs[R][Hd];
    int row0 = blockIdx.x * R;
    int c = threadIdx.x;   // 128 threads
    for (int idx = c; idx < R*Hd; idx += 128) {
        int r = idx >> 7, k = idx & 127;
        float yv = g_y[(size_t)(row0+r)*Hd + k];
        // tanh gelu (jax approximate=True)
        float t = 0.7978845608028654f * (yv + 0.044715f * yv*yv*yv);
        zs[r][k] = 0.5f * yv * (1.0f + tanhf(t));
    }
    __syncthreads();
    float acc1[R], acc2[R];
    float bv1 = b1[c], bv2 = b2[c];
    #pragma unroll
    for (int r = 0; r < R; r++) { acc1[r] = bv1; acc2[r] = bv2; }
    for (int k = 0; k < Hd; k++) {
        float w1v = w1[c*Hd + k];
        float w2v = w2[c*Hd + k];
        #pragma unroll
        for (int r = 0; r < R; r++) {
            float z = zs[r][k];
            acc1[r] = fmaf(z, w1v, acc1[r]);
            acc2[r] = fmaf(z, w2v, acc2[r]);
        }
    }
    #pragma unroll
    for (int r = 0; r < R; r++) {
        float sig = 1.0f / (1.0f + __expf(-acc2[r]));
        float o = acc1[r] * sig;
        size_t idx = (size_t)(row0+r)*Hd + c;
        g_h[idx] = g_h[idx] + o;   // skip + y
    }
}

// ---------------- decoder ----------------
__global__ void dec_kernel(const float* __restrict__ w, const float* __restrict__ bias,
                           float* __restrict__ out) {
    const int R = 32;
    __shared__ float hs[R][Hd];
    int row0 = blockIdx.x * R;
    for (int idx = threadIdx.x; idx < R*Hd; idx += 128)
        hs[idx >> 7][idx & 127] = g_h[(size_t)(row0 + (idx>>7))*Hd + (idx & 127)];
    __syncthreads();
    int o = threadIdx.x & 63;
    int r0 = (threadIdx.x >> 6) * 16;
    float acc[16];
    float bv = bias[o];
    #pragma unroll
    for (int r = 0; r < 16; r++) acc[r] = bv;
    for (int k = 0; k < Hd; k++) {
        float wv = w[o*Hd + k];
        #pragma unroll
        for (int r = 0; r < 16; r++) acc[r] = fmaf(hs[r0+r][k], wv, acc[r]);
    }
    #pragma unroll
    for (int r = 0; r < 16; r++)
        out[(size_t)(row0 + r0 + r)*OUTF + o] = acc[r];
}

// ---------------- launch ----------------
extern "C" void kernel_launch(void* const* d_in, const int* in_sizes, int n_in,
                              void* d_out, int out_size) {
    const float* x       = (const float*)d_in[0];
    // d_in[1] = convolve (static 1) — FFT conv path
    const float* enc_w   = (const float*)d_in[2];
    const float* enc_b   = (const float*)d_in[3];
    const float* dec_w   = (const float*)d_in[4];
    const float* dec_b   = (const float*)d_in[5];
    const float* lam_re  = (const float*)d_in[6];
    const float* lam_im  = (const float*)d_in[7];
    const float* p_re    = (const float*)d_in[8];
    const float* p_im    = (const float*)d_in[9];
    const float* b_re    = (const float*)d_in[10];
    const float* b_im    = (const float*)d_in[11];
    const float* c_re    = (const float*)d_in[12];
    const float* c_im    = (const float*)d_in[13];
    const float* dvec    = (const float*)d_in[14];
    const float* logstep = (const float*)d_in[15];
    const float* norm_w  = (const float*)d_in[16];
    const float* norm_b  = (const float*)d_in[17];
    const float* w1      = (const float*)d_in[18];
    const float* b1      = (const float*)d_in[19];
    const float* w2      = (const float*)d_in[20];
    const float* b2      = (const float*)d_in[21];
    float* out = (float*)d_out;

    int smem = 2 * L2 * (int)sizeof(float2);  // 64 KB
    cudaFuncSetAttribute(kfft_kernel, cudaFuncAttributeMaxDynamicSharedMemorySize, smem);
    cudaFuncSetAttribute(conv_kernel, cudaFuncAttributeMaxDynamicSharedMemorySize, smem);

    twiddle_kernel<<<(L2/2 + 255)/256, 256>>>();
    encoder_kernel<<<ROWS/16, 128>>>(x, enc_w, enc_b);
    for (int i = 0; i < NLAY; i++) {
        ln_kernel<<<ROWS/8, 256>>>(norm_w + i*Hd, norm_b + i*Hd);
        cauchy_kernel<<<Hd, 256>>>(lam_re + i*Hd*Nst, lam_im + i*Hd*Nst,
                                   p_re  + i*Hd*Nst, p_im  + i*Hd*Nst,
                                   b_re  + i*Hd*Nst, b_im  + i*Hd*Nst,
                                   c_re  + i*Hd*Nst, c_im  + i*Hd*Nst,
                                   logstep + i*Hd);
        kfft_kernel<<<Hd, 256, smem>>>();
        conv_kernel<<<Bsz*Hd, 256, smem>>>(dvec + i*Hd);
        mlp_kernel<<<ROWS/16, 128>>>(w1 + i*Hd*Hd, b1 + i*Hd, w2 + i*Hd*Hd, b2 + i*Hd);
    }
    dec_kernel<<<ROWS/32, 128>>>(dec_w, dec_b, out);
}

// round 3
// speedup vs baseline: 1.5390x; 1.5390x over previous
#include <cuda_runtime.h>
#include <math.h>

#define Bsz 8
#define Lseq 2048
#define INF 64
#define OUTF 64
#define Hd 128
#define Nst 64
#define NLAY 4
#define L2 4096
#define ROWS (Bsz*Lseq)

// ---------------- persistent scratch ----------------
__device__ float  g_h  [ROWS*Hd];        // activations (B,L,H)
__device__ float  g_hnT[Bsz*Hd*Lseq];    // layernormed, transposed (B,H,L)
__device__ float  g_yT [Bsz*Hd*Lseq];    // conv output, transposed (B,H,L)
__device__ float2 g_at [Hd*Lseq];        // at_roots (H, L) complex
__device__ float2 g_Kd [Hd*L2];          // kernel spectrum (H, 4096) complex
__device__ float2 g_tw [L2/2];           // twiddles W_4096^m = exp(-2pi i m/4096), m < 2048

__device__ __forceinline__ float2 cmulf(float2 a, float2 b) {
    return make_float2(a.x*b.x - a.y*b.y, a.x*b.y + a.y*b.x);
}
__device__ __forceinline__ float2 caddf(float2 a, float2 b){ return make_float2(a.x+b.x, a.y+b.y); }
__device__ __forceinline__ float2 csubf(float2 a, float2 b){ return make_float2(a.x-b.x, a.y-b.y); }
// a + sgn*i*d
__device__ __forceinline__ float2 addi(float2 a, float2 d, float sgn) {
    return make_float2(a.x - sgn*d.y, a.y + sgn*d.x);
}

// ---------------- twiddle table ----------------
__global__ void twiddle_kernel() {
    int m = blockIdx.x * blockDim.x + threadIdx.x;
    if (m < L2/2) {
        float s, c;
        sincospif(-(float)m / 2048.0f, &s, &c);
        g_tw[m] = make_float2(c, s);
    }
}

// ---------------- radix-4 (mixed final radix-2) Stockham FFT, in-smem ----------------
// n = 4096 (6 radix-4 stages) or 2048 (5 radix-4 + 1 radix-2). Result always lands in `a`.
__device__ float2* fftN(float2* a, float2* b, int n, bool inverse) {
    float2* src = a; float2* dst = b;
    const int q = n >> 2;
    const int nst4 = (n == 4096) ? 6 : 5;
    const float sgnF = inverse ? 1.0f : -1.0f;   // sign of i in X1
    int Ls = 1, mult = 1024;                      // twiddle index multiplier: W_{4Ls}^k = W_4096^{k*1024/Ls}
    for (int t = 0; t < nst4; t++) {
        __syncthreads();
        for (int j = threadIdx.x; j < q; j += blockDim.x) {
            int k = j & (Ls - 1);
            int blk = j >> (2*t);
            float2 u0 = src[j], u1 = src[j+q], u2 = src[j+2*q], u3 = src[j+3*q];
            float2 w1 = g_tw[k * mult];
            if (inverse) w1.y = -w1.y;
            float2 w2 = cmulf(w1, w1);
            float2 w3 = cmulf(w2, w1);
            float2 t1 = cmulf(w1, u1), t2 = cmulf(w2, u2), t3 = cmulf(w3, u3);
            float2 a02 = caddf(u0, t2), s02 = csubf(u0, t2);
            float2 a13 = caddf(t1, t3), s13 = csubf(t1, t3);
            int o = (blk << (2*t + 2)) + k;
            dst[o       ] = caddf(a02, a13);
            dst[o +   Ls] = addi(s02, s13, sgnF);
            dst[o + 2*Ls] = csubf(a02, a13);
            dst[o + 3*Ls] = addi(s02, s13, -sgnF);
        }
        { float2* tmp = src; src = dst; dst = tmp; }
        Ls <<= 2; mult >>= 2;
    }
    if (n == 2048) {  // final radix-2, Ls=1024, twiddle W_2048^k = W_4096^{2k}
        __syncthreads();
        for (int j = threadIdx.x; j < 1024; j += blockDim.x) {
            float2 u = src[j], v = src[j + 1024];
            float2 w = g_tw[2*j];
            if (inverse) w.y = -w.y;
            float2 tv = cmulf(w, v);
            dst[j]        = caddf(u, tv);
            dst[j + 1024] = csubf(u, tv);
        }
        { float2* tmp = src; src = dst; dst = tmp; }
    }
    __syncthreads();
    return src;
}

// ---------------- encoder: h = x @ enc_w.T + enc_b ----------------
__global__ void encoder_kernel(const float* __restrict__ x,
                               const float* __restrict__ w,
                               const float* __restrict__ bias) {
    const int R = 16;
    __shared__ float xs[R][INF];
    int row0 = blockIdx.x * R;
    int c = threadIdx.x;
    for (int idx = c; idx < R*INF; idx += 128)
        xs[idx / INF][idx % INF] = x[(row0 + idx/INF)*INF + (idx % INF)];
    __syncthreads();
    float acc[R];
    float bv = bias[c];
    #pragma unroll
    for (int r = 0; r < R; r++) acc[r] = bv;
    for (int k = 0; k < INF; k++) {
        float wv = w[c*INF + k];
        #pragma unroll
        for (int r = 0; r < R; r++) acc[r] = fmaf(xs[r][k], wv, acc[r]);
    }
    #pragma unroll
    for (int r = 0; r < R; r++) g_h[(size_t)(row0+r)*Hd + c] = acc[r];
}

// ---------------- layernorm over H, fused transpose -> g_hnT (B,H,L) ----------------
__global__ void ln_t_kernel(const float* __restrict__ nw, const float* __restrict__ nb) {
    __shared__ float tile[32][129];
    int row0 = blockIdx.x * 32;
    int b = row0 >> 11, l0 = row0 & 2047;
    int warp = threadIdx.x >> 5, lane = threadIdx.x & 31;
    #pragma unroll
    for (int rr = 0; rr < 4; rr++) {
        int l = warp*4 + rr;
        const float* row = g_h + (size_t)(row0 + l)*Hd;
        float v[4]; float sum = 0.f;
        #pragma unroll
        for (int i = 0; i < 4; i++) { v[i] = row[lane + 32*i]; sum += v[i]; }
        #pragma unroll
        for (int o = 16; o; o >>= 1) sum += __shfl_xor_sync(0xffffffffu, sum, o);
        float mu = sum * (1.0f/Hd);
        float var = 0.f;
        #pragma unroll
        for (int i = 0; i < 4; i++) { float t = v[i]-mu; var += t*t; }
        #pragma unroll
        for (int o = 16; o; o >>= 1) var += __shfl_xor_sync(0xffffffffu, var, o);
        var *= (1.0f/Hd);
        float rstd = rsqrtf(var + 1e-5f);
        #pragma unroll
        for (int i = 0; i < 4; i++) {
            int c = lane + 32*i;
            tile[l][c] = (v[i]-mu)*rstd*nw[c] + nb[c];
        }
    }
    __syncthreads();
    for (int idx = threadIdx.x; idx < 32*Hd; idx += 256) {
        int h = idx >> 5, l = idx & 31;
        g_hnT[((size_t)(b*Hd + h))*Lseq + l0 + l] = tile[l][h];
    }
}

// ---------------- cauchy / woodbury: at_roots (H, L) ----------------
__global__ void cauchy_kernel(const float* __restrict__ lre, const float* __restrict__ lim,
                              const float* __restrict__ pre, const float* __restrict__ pim,
                              const float* __restrict__ bre, const float* __restrict__ bim,
                              const float* __restrict__ cre, const float* __restrict__ cim,
                              const float* __restrict__ lstep) {
    int h = blockIdx.x;
    int l0 = blockIdx.y * 512;
    __shared__ float2 slam[Nst], s00[Nst], s01[Nst], s10[Nst], s11[Nst];
    int tid = threadIdx.x;
    if (tid < Nst) {
        int idx = h*Nst + tid;
        slam[tid] = make_float2(lre[idx], lim[idx]);
        float2 P  = make_float2(pre[idx], pim[idx]);
        float2 Bv = make_float2(bre[idx], bim[idx]);
        float2 Cc = make_float2(cre[idx], -cim[idx]);
        float2 Pc = make_float2(P.x, -P.y);
        s00[tid] = cmulf(Cc, Bv);
        s01[tid] = cmulf(Cc, P);
        s10[tid] = cmulf(Pc, Bv);
        s11[tid] = cmulf(Pc, P);
    }
    __syncthreads();
    float ts = 2.0f / __expf(lstep[h]);
    for (int l = l0 + tid; l < l0 + 512; l += blockDim.x) {
        // XLA-style omega: f32-rounded angle + sincosf (l=L/2 must NOT hit exactly -1)
        float ang = -6.2831853071795864f * ((float)l / (float)Lseq);
        float s, c;
        sincosf(ang, &s, &c);
        float dpx = 1.0f + c, dpy = s;
        float dmx = 1.0f - c, dmy = -s;
        float id2 = __fdividef(1.0f, dpx*dpx + dpy*dpy);
        float gx = ts * (dmx*dpx + dmy*dpy) * id2;
        float gy = ts * (dmy*dpx - dmx*dpy) * id2;
        float c2x = 2.0f*dpx*id2, c2y = -2.0f*dpy*id2;
        float k00x=0,k00y=0,k01x=0,k01y=0,k10x=0,k10y=0,k11x=0,k11y=0;
        #pragma unroll 8
        for (int n = 0; n < Nst; n++) {
            float dx = gx - slam[n].x;
            float dy = gy - slam[n].y;
            float inv = __fdividef(1.0f, dx*dx + dy*dy);
            float rx = dx*inv, ry = -dy*inv;
            float2 v;
            v = s00[n]; k00x += v.x*rx - v.y*ry; k00y += v.x*ry + v.y*rx;
            v = s01[n]; k01x += v.x*rx - v.y*ry; k01y += v.x*ry + v.y*rx;
            v = s10[n]; k10x += v.x*rx - v.y*ry; k10y += v.x*ry + v.y*rx;
            v = s11[n]; k11x += v.x*rx - v.y*ry; k11y += v.x*ry + v.y*rx;
        }
        float opx = 1.0f + k11x, opy = k11y;
        float oinv = __fdividef(1.0f, opx*opx + opy*opy);
        float wx = k01x*k10x - k01y*k10y;
        float wy = k01x*k10y + k01y*k10x;
        float cx = (wx*opx + wy*opy) * oinv;
        float cy = (wy*opx - wx*opy) * oinv;
        float rx = k00x - cx, ry = k00y - cy;
        g_at[h*Lseq + l] = make_float2(c2x*rx - c2y*ry, c2x*ry + c2y*rx);
    }
}

// ---------------- Kd (4096 bins) from at_roots via split even/odd bins ----------------
// x = IFFT_2048(at)/2048 (real part). Kd[2m] = (at[m]+conj(at[-m]))/2 (exact symmetrization);
// Kd[2m+1] = FFT_2048(Re(x) * W_4096^l)[m].
__global__ void kfft_kernel() {
    extern __shared__ float2 sm[];
    float2* A  = sm;
    float2* Bb = sm + Lseq;
    int h = blockIdx.x;
    int tid = threadIdx.x;
    const float2* at = g_at + (size_t)h*Lseq;
    for (int l = tid; l < Lseq; l += blockDim.x) A[l] = at[l];
    float2* r = fftN(A, Bb, Lseq, true);  // unnormalized inverse; result in A
    // even bins (from global at, r untouched) + build xw into Bb
    for (int m = tid; m < Lseq; m += blockDim.x) {
        float2 am = at[m];
        float2 ar = at[(Lseq - m) & (Lseq-1)];
        g_Kd[(size_t)h*L2 + 2*m] = make_float2(0.5f*(am.x + ar.x), 0.5f*(am.y - ar.y));
        float xr = r[m].x * (1.0f/Lseq);
        float2 w = g_tw[m];               // W_4096^m
        Bb[m] = make_float2(xr * w.x, xr * w.y);
    }
    float2* r2 = fftN(Bb, A, Lseq, false);  // result in Bb
    for (int m = tid; m < Lseq; m += blockDim.x)
        g_Kd[(size_t)h*L2 + 2*m + 1] = r2[m];
}

// ---------------- FFT causal conv, two real channels packed per complex FFT ----------------
__global__ void conv_kernel(const float* __restrict__ dvec) {
    extern __shared__ float2 sm[];
    float2* A  = sm;
    float2* Bb = sm + L2;
    int blk = blockIdx.x;
    int b = blk >> 6, hp = blk & 63;
    int h0 = 2*hp;
    int tid = threadIdx.x;
    const float* u1 = g_hnT + ((size_t)b*Hd + h0)*Lseq;
    const float* u2 = u1 + Lseq;
    for (int l = tid; l < L2; l += blockDim.x)
        A[l] = (l < Lseq) ? make_float2(u1[l], u2[l]) : make_float2(0.f, 0.f);
    float2* Z = fftN(A, Bb, L2, false);   // in A
    const float2* K1 = g_Kd + (size_t)h0*L2;
    const float2* K2 = K1 + L2;
    for (int f = tid; f < L2; f += blockDim.x) {
        int fr = (L2 - f) & (L2-1);
        float2 zf = Z[f], zr = Z[fr];
        float2 U1 = make_float2(0.5f*(zf.x + zr.x),  0.5f*(zf.y - zr.y));
        float2 U2 = make_float2(0.5f*(zf.y + zr.y), -0.5f*(zf.x - zr.x));
        float2 Y1 = cmulf(U1, K1[f]);
        float2 Y2 = cmulf(U2, K2[f]);
        Bb[f] = make_float2(Y1.x - Y2.y, Y1.y + Y2.x);   // Y1 + i*Y2
    }
    float2* w = fftN(Bb, A, L2, true);    // in Bb (fftN syncs before reading)
    float d1 = dvec[h0], d2 = dvec[h0+1];
    float* y1 = g_yT + ((size_t)b*Hd + h0)*Lseq;
    float* y2 = y1 + Lseq;
    for (int l = tid; l < Lseq; l += blockDim.x) {
        y1[l] = w[l].x*(1.0f/L2) + u1[l]*d1;
        y2[l] = w[l].y*(1.0f/L2) + u2[l]*d2;
    }
}

// ---------------- gelu + gated MLP + residual (reads yT transposed) ----------------
__global__ void mlp_kernel(const float* __restrict__ w1, const float* __restrict__ b1,
                           const float* __restrict__ w2, const float* __restrict__ b2) {
    const int R = 16;
    __shared__ float zs[R][Hd+1];
    int row0 = blockIdx.x * R;
    int b = row0 >> 11, l0 = row0 & 2047;
    int c = threadIdx.x;
    for (int idx = c; idx < R*Hd; idx += 128) {
        int k = idx >> 4, r = idx & 15;
        float yv = g_yT[((size_t)(b*Hd + k))*Lseq + l0 + r];
        float t = 0.7978845608028654f * (yv + 0.044715f * yv*yv*yv);
        zs[r][k] = 0.5f * yv * (1.0f + tanhf(t));
    }
    __syncthreads();
    float acc1[R], acc2[R];
    float bv1 = b1[c], bv2 = b2[c];
    #pragma unroll
    for (int r = 0; r < R; r++) { acc1[r] = bv1; acc2[r] = bv2; }
    for (int k = 0; k < Hd; k++) {
        float w1v = w1[c*Hd + k];
        float w2v = w2[c*Hd + k];
        #pragma unroll
        for (int r = 0; r < R; r++) {
            float z = zs[r][k];
            acc1[r] = fmaf(z, w1v, acc1[r]);
            acc2[r] = fmaf(z, w2v, acc2[r]);
        }
    }
    #pragma unroll
    for (int r = 0; r < R; r++) {
        float sig = 1.0f / (1.0f + __expf(-acc2[r]));
        float o = acc1[r] * sig;
        size_t idx = (size_t)(row0+r)*Hd + c;
        g_h[idx] = g_h[idx] + o;
    }
}

// ---------------- decoder ----------------
__global__ void dec_kernel(const float* __restrict__ w, const float* __restrict__ bias,
                           float* __restrict__ out) {
    const int R = 32;
    __shared__ float hs[R][Hd];
    int row0 = blockIdx.x * R;
    for (int idx = threadIdx.x; idx < R*Hd; idx += 128)
        hs[idx >> 7][idx & 127] = g_h[(size_t)(row0 + (idx>>7))*Hd + (idx & 127)];
    __syncthreads();
    int o = threadIdx.x & 63;
    int r0 = (threadIdx.x >> 6) * 16;
    float acc[16];
    float bv = bias[o];
    #pragma unroll
    for (int r = 0; r < 16; r++) acc[r] = bv;
    for (int k = 0; k < Hd; k++) {
        float wv = w[o*Hd + k];
        #pragma unroll
        for (int r = 0; r < 16; r++) acc[r] = fmaf(hs[r0+r][k], wv, acc[r]);
    }
    #pragma unroll
    for (int r = 0; r < 16; r++)
        out[(size_t)(row0 + r0 + r)*OUTF + o] = acc[r];
}

// ---------------- launch ----------------
extern "C" void kernel_launch(void* const* d_in, const int* in_sizes, int n_in,
                              void* d_out, int out_size) {
    const float* x       = (const float*)d_in[0];
    const float* enc_w   = (const float*)d_in[2];
    const float* enc_b   = (const float*)d_in[3];
    const float* dec_w   = (const float*)d_in[4];
    const float* dec_b   = (const float*)d_in[5];
    const float* lam_re  = (const float*)d_in[6];
    const float* lam_im  = (const float*)d_in[7];
    const float* p_re    = (const float*)d_in[8];
    const float* p_im    = (const float*)d_in[9];
    const float* b_re    = (const float*)d_in[10];
    const float* b_im    = (const float*)d_in[11];
    const float* c_re    = (const float*)d_in[12];
    const float* c_im    = (const float*)d_in[13];
    const float* dvec    = (const float*)d_in[14];
    const float* logstep = (const float*)d_in[15];
    const float* norm_w  = (const float*)d_in[16];
    const float* norm_b  = (const float*)d_in[17];
    const float* w1      = (const float*)d_in[18];
    const float* b1      = (const float*)d_in[19];
    const float* w2      = (const float*)d_in[20];
    const float* b2      = (const float*)d_in[21];
    float* out = (float*)d_out;

    int smem_conv = 2 * L2   * (int)sizeof(float2);  // 64 KB
    int smem_kfft = 2 * Lseq * (int)sizeof(float2);  // 32 KB
    cudaFuncSetAttribute(kfft_kernel, cudaFuncAttributeMaxDynamicSharedMemorySize, smem_kfft);
    cudaFuncSetAttribute(conv_kernel, cudaFuncAttributeMaxDynamicSharedMemorySize, smem_conv);

    twiddle_kernel<<<8, 256>>>();
    encoder_kernel<<<ROWS/16, 128>>>(x, enc_w, enc_b);
    for (int i = 0; i < NLAY; i++) {
        ln_t_kernel<<<ROWS/32, 256>>>(norm_w + i*Hd, norm_b + i*Hd);
        cauchy_kernel<<<dim3(Hd,4), 256>>>(lam_re + i*Hd*Nst, lam_im + i*Hd*Nst,
                                           p_re  + i*Hd*Nst, p_im  + i*Hd*Nst,
                                           b_re  + i*Hd*Nst, b_im  + i*Hd*Nst,
                                           c_re  + i*Hd*Nst, c_im  + i*Hd*Nst,
                                           logstep + i*Hd);
        kfft_kernel<<<Hd, 256, smem_kfft>>>();
        conv_kernel<<<Bsz*Hd/2, 256, smem_conv>>>(dvec + i*Hd);
        mlp_kernel<<<ROWS/16, 128>>>(w1 + i*Hd*Hd, b1 + i*Hd, w2 + i*Hd*Hd, b2 + i*Hd);
    }
    dec_kernel<<<ROWS/32, 128>>>(dec_w, dec_b, out);
}

// round 6
// speedup vs baseline: 3.0476x; 1.9803x over previous
#include <cuda_runtime.h>
#include <math.h>

#define Bsz 8
#define Lseq 2048
#define INF 64
#define OUTF 64
#define Hd 128
#define Nst 64
#define NLAY 4
#define L2 4096
#define ROWS (Bsz*Lseq)

typedef unsigned long long ull;

// ---------------- persistent scratch ----------------
__device__ float  g_h  [ROWS*Hd];        // activations (B,L,H)
__device__ float  g_hnT[Bsz*Hd*Lseq];    // layernormed, transposed (B,H,L)
__device__ float  g_yT [Bsz*Hd*Lseq];    // gelu(conv output), transposed (B,H,L)
__device__ float2 g_at [Hd*Lseq];        // at_roots (H, L) complex
__device__ float2 g_Kd [Hd*L2];          // kernel spectrum (H, 4096) complex
__device__ float2 g_tw [L2/2];           // twiddles W_4096^m, m < 2048
__device__ float  g_w1T[NLAY*Hd*Hd];     // transposed weights [k][c]
__device__ float  g_w2T[NLAY*Hd*Hd];
__device__ float  g_encWT[INF*Hd];
__device__ float  g_decWT[Hd*OUTF];

__device__ __forceinline__ float2 cmulf(float2 a, float2 b) {
    return make_float2(a.x*b.x - a.y*b.y, a.x*b.y + a.y*b.x);
}
__device__ __forceinline__ float2 caddf(float2 a, float2 b){ return make_float2(a.x+b.x, a.y+b.y); }
__device__ __forceinline__ float2 csubf(float2 a, float2 b){ return make_float2(a.x-b.x, a.y-b.y); }
__device__ __forceinline__ float2 addi(float2 a, float2 d, float sgn) {
    return make_float2(a.x - sgn*d.y, a.y + sgn*d.x);
}
// ---- packed f32x2 helpers ----
__device__ __forceinline__ ull pk(float x, float y) {
    ull r; asm("mov.b64 %0, {%1, %2};" : "=l"(r) : "f"(x), "f"(y)); return r;
}
__device__ __forceinline__ void upk(ull p, float& x, float& y) {
    asm("mov.b64 {%0, %1}, %2;" : "=f"(x), "=f"(y) : "l"(p));
}
__device__ __forceinline__ ull ffma2(ull a, ull b, ull c) {
    ull d; asm("fma.rn.f32x2 %0, %1, %2, %3;" : "=l"(d) : "l"(a), "l"(b), "l"(c)); return d;
}

// ---------------- twiddle + weight transpose prep ----------------
__global__ void twiddle_kernel() {
    int m = blockIdx.x * blockDim.x + threadIdx.x;
    if (m < L2/2) {
        float s, c;
        sincospif(-(float)m / 2048.0f, &s, &c);
        g_tw[m] = make_float2(c, s);
    }
}
__global__ void prep_kernel(const float* __restrict__ enc_w, const float* __restrict__ dec_w,
                            const float* __restrict__ w1, const float* __restrict__ w2) {
    int tid = blockIdx.x * 256 + threadIdx.x;
    if (tid < INF*Hd) { int k = tid >> 7, c = tid & 127; g_encWT[tid] = enc_w[c*INF + k]; }
    if (tid < Hd*OUTF) { int k = tid >> 6, o = tid & 63; g_decWT[tid] = dec_w[o*Hd + k]; }
    if (tid < NLAY*Hd*Hd) {
        int lay = tid >> 14, r = tid & 16383, k = r >> 7, c = r & 127;
        g_w1T[tid] = w1[lay*Hd*Hd + c*Hd + k];
        g_w2T[tid] = w2[lay*Hd*Hd + c*Hd + k];
    }
}

// ---------------- radix-4 (mixed final radix-2) Stockham FFT, in-smem ----------------
__device__ float2* fftN(float2* a, float2* b, int n, bool inverse) {
    float2* src = a; float2* dst = b;
    const int q = n >> 2;
    const int nst4 = (n == 4096) ? 6 : 5;
    const float sgnF = inverse ? 1.0f : -1.0f;
    int Ls = 1, mult = 1024;
    for (int t = 0; t < nst4; t++) {
        __syncthreads();
        for (int j = threadIdx.x; j < q; j += blockDim.x) {
            int k = j & (Ls - 1);
            int blk = j >> (2*t);
            float2 u0 = src[j], u1 = src[j+q], u2 = src[j+2*q], u3 = src[j+3*q];
            float2 w1 = g_tw[k * mult];
            if (inverse) w1.y = -w1.y;
            float2 w2 = cmulf(w1, w1);
            float2 w3 = cmulf(w2, w1);
            float2 t1 = cmulf(w1, u1), t2 = cmulf(w2, u2), t3 = cmulf(w3, u3);
            float2 a02 = caddf(u0, t2), s02 = csubf(u0, t2);
            float2 a13 = caddf(t1, t3), s13 = csubf(t1, t3);
            int o = (blk << (2*t + 2)) + k;
            dst[o       ] = caddf(a02, a13);
            dst[o +   Ls] = addi(s02, s13, sgnF);
            dst[o + 2*Ls] = csubf(a02, a13);
            dst[o + 3*Ls] = addi(s02, s13, -sgnF);
        }
        { float2* tmp = src; src = dst; dst = tmp; }
        Ls <<= 2; mult >>= 2;
    }
    if (n == 2048) {
        __syncthreads();
        for (int j = threadIdx.x; j < 1024; j += blockDim.x) {
            float2 u = src[j], v = src[j + 1024];
            float2 w = g_tw[2*j];
            if (inverse) w.y = -w.y;
            float2 tv = cmulf(w, v);
            dst[j]        = caddf(u, tv);
            dst[j + 1024] = csubf(u, tv);
        }
        { float2* tmp = src; src = dst; dst = tmp; }
    }
    __syncthreads();
    return src;
}

// ---------------- encoder: h = x @ enc_w.T + enc_b (coalesced transposed weights) ----------------
__global__ void encoder_kernel(const float* __restrict__ x,
                               const float* __restrict__ bias) {
    const int R = 16;
    __shared__ float xs[R][INF];
    int row0 = blockIdx.x * R;
    int c = threadIdx.x;  // 128 threads = output channel
    for (int idx = c; idx < R*INF; idx += 128)
        xs[idx / INF][idx % INF] = x[(size_t)(row0 + idx/INF)*INF + (idx % INF)];
    __syncthreads();
    float acc[R];
    float bv = bias[c];
    #pragma unroll
    for (int r = 0; r < R; r++) acc[r] = bv;
    for (int k = 0; k < INF; k++) {
        float wv = g_encWT[k*Hd + c];
        #pragma unroll
        for (int r = 0; r < R; r++) acc[r] = fmaf(xs[r][k], wv, acc[r]);
    }
    #pragma unroll
    for (int r = 0; r < R; r++) g_h[(size_t)(row0+r)*Hd + c] = acc[r];
}

// ---------------- layernorm over H, fused transpose -> g_hnT (B,H,L) ----------------
__global__ void ln_t_kernel(const float* __restrict__ nw, const float* __restrict__ nb) {
    __shared__ float tile[32][129];
    int row0 = blockIdx.x * 32;
    int b = row0 >> 11, l0 = row0 & 2047;
    int warp = threadIdx.x >> 5, lane = threadIdx.x & 31;
    #pragma unroll
    for (int rr = 0; rr < 4; rr++) {
        int l = warp*4 + rr;
        const float* row = g_h + (size_t)(row0 + l)*Hd;
        float v[4]; float sum = 0.f;
        #pragma unroll
        for (int i = 0; i < 4; i++) { v[i] = row[lane + 32*i]; sum += v[i]; }
        #pragma unroll
        for (int o = 16; o; o >>= 1) sum += __shfl_xor_sync(0xffffffffu, sum, o);
        float mu = sum * (1.0f/Hd);
        float var = 0.f;
        #pragma unroll
        for (int i = 0; i < 4; i++) { float t = v[i]-mu; var += t*t; }
        #pragma unroll
        for (int o = 16; o; o >>= 1) var += __shfl_xor_sync(0xffffffffu, var, o);
        var *= (1.0f/Hd);
        float rstd = rsqrtf(var + 1e-5f);
        #pragma unroll
        for (int i = 0; i < 4; i++) {
            int c = lane + 32*i;
            tile[l][c] = (v[i]-mu)*rstd*nw[c] + nb[c];
        }
    }
    __syncthreads();
    for (int idx = threadIdx.x; idx < 32*Hd; idx += 256) {
        int h = idx >> 5, l = idx & 31;
        g_hnT[((size_t)(b*Hd + h))*Lseq + l0 + l] = tile[l][h];
    }
}

// ---------------- cauchy / woodbury with f32x2 accumulation ----------------
__global__ void cauchy_kernel(const float* __restrict__ lre, const float* __restrict__ lim,
                              const float* __restrict__ pre, const float* __restrict__ pim,
                              const float* __restrict__ bre, const float* __restrict__ bim,
                              const float* __restrict__ cre, const float* __restrict__ cim,
                              const float* __restrict__ lstep) {
    int h = blockIdx.x;
    int l0 = blockIdx.y * 512;
    __shared__ float2 slam[Nst];
    __shared__ ull sp[4][Nst][2];   // per matrix: (vx,vy), (vy,-vx)
    int tid = threadIdx.x;
    if (tid < Nst) {
        int idx = h*Nst + tid;
        slam[tid] = make_float2(lre[idx], lim[idx]);
        float2 P  = make_float2(pre[idx], pim[idx]);
        float2 Bv = make_float2(bre[idx], bim[idx]);
        float2 Cc = make_float2(cre[idx], -cim[idx]);
        float2 Pc = make_float2(P.x, -P.y);
        float2 vm[4];
        vm[0] = cmulf(Cc, Bv); vm[1] = cmulf(Cc, P);
        vm[2] = cmulf(Pc, Bv); vm[3] = cmulf(Pc, P);
        #pragma unroll
        for (int m = 0; m < 4; m++) {
            sp[m][tid][0] = pk(vm[m].x, vm[m].y);
            sp[m][tid][1] = pk(vm[m].y, -vm[m].x);
        }
    }
    __syncthreads();
    float ts = 2.0f / __expf(lstep[h]);
    for (int l = l0 + tid; l < l0 + 512; l += blockDim.x) {
        // XLA-style omega (f32 angle + sincosf; l=L/2 must NOT be exactly -1)
        float ang = -6.2831853071795864f * ((float)l / (float)Lseq);
        float s, c;
        sincosf(ang, &s, &c);
        float dpx = 1.0f + c, dpy = s;
        float dmx = 1.0f - c, dmy = -s;
        float id2 = __fdividef(1.0f, dpx*dpx + dpy*dpy);
        float gx = ts * (dmx*dpx + dmy*dpy) * id2;
        float gy = ts * (dmy*dpx - dmx*dpy) * id2;
        float c2x = 2.0f*dpx*id2, c2y = -2.0f*dpy*id2;
        ull acc[4] = {0ull, 0ull, 0ull, 0ull};   // (kx, ky) pairs
        #pragma unroll 8
        for (int n = 0; n < Nst; n++) {
            float dx = gx - slam[n].x;
            float dy = gy - slam[n].y;
            float inv = __fdividef(1.0f, dx*dx + dy*dy);
            float rx = dx*inv, ryp = dy*inv;     // actual ry = -ryp
            ull rxx = pk(rx, rx), ryy = pk(ryp, ryp);
            #pragma unroll
            for (int m = 0; m < 4; m++)
                acc[m] = ffma2(sp[m][n][0], rxx, ffma2(sp[m][n][1], ryy, acc[m]));
        }
        float k00x,k00y,k01x,k01y,k10x,k10y,k11x,k11y;
        upk(acc[0], k00x, k00y); upk(acc[1], k01x, k01y);
        upk(acc[2], k10x, k10y); upk(acc[3], k11x, k11y);
        float opx = 1.0f + k11x, opy = k11y;
        float oinv = __fdividef(1.0f, opx*opx + opy*opy);
        float wx = k01x*k10x - k01y*k10y;
        float wy = k01x*k10y + k01y*k10x;
        float cx = (wx*opx + wy*opy) * oinv;
        float cy = (wy*opx - wx*opy) * oinv;
        float rx2 = k00x - cx, ry2 = k00y - cy;
        g_at[h*Lseq + l] = make_float2(c2x*rx2 - c2y*ry2, c2x*ry2 + c2y*rx2);
    }
}

// ---------------- Kd (4096 bins) from at_roots via even/odd bin split ----------------
__global__ void kfft_kernel() {
    extern __shared__ float2 sm[];
    float2* A  = sm;
    float2* Bb = sm + Lseq;
    int h = blockIdx.x;
    int tid = threadIdx.x;
    const float2* at = g_at + (size_t)h*Lseq;
    for (int l = tid; l < Lseq; l += blockDim.x) A[l] = at[l];
    float2* r = fftN(A, Bb, Lseq, true);
    for (int m = tid; m < Lseq; m += blockDim.x) {
        float2 am = at[m];
        float2 ar = at[(Lseq - m) & (Lseq-1)];
        g_Kd[(size_t)h*L2 + 2*m] = make_float2(0.5f*(am.x + ar.x), 0.5f*(am.y - ar.y));
        float xr = r[m].x * (1.0f/Lseq);
        float2 w = g_tw[m];
        Bb[m] = make_float2(xr * w.x, xr * w.y);
    }
    float2* r2 = fftN(Bb, A, Lseq, false);
    for (int m = tid; m < Lseq; m += blockDim.x)
        g_Kd[(size_t)h*L2 + 2*m + 1] = r2[m];
}

// ---------------- FFT causal conv (2 real channels packed) + fused gelu ----------------
__global__ void conv_kernel(const float* __restrict__ dvec) {
    extern __shared__ float2 sm[];
    float2* A  = sm;
    float2* Bb = sm + L2;
    int blk = blockIdx.x;
    int b = blk >> 6, hp = blk & 63;
    int h0 = 2*hp;
    int tid = threadIdx.x;
    const float* u1 = g_hnT + ((size_t)b*Hd + h0)*Lseq;
    const float* u2 = u1 + Lseq;
    for (int l = tid; l < L2; l += blockDim.x)
        A[l] = (l < Lseq) ? make_float2(u1[l], u2[l]) : make_float2(0.f, 0.f);
    float2* Z = fftN(A, Bb, L2, false);
    const float2* K1 = g_Kd + (size_t)h0*L2;
    const float2* K2 = K1 + L2;
    for (int f = tid; f < L2; f += blockDim.x) {
        int fr = (L2 - f) & (L2-1);
        float2 zf = Z[f], zr = Z[fr];
        float2 U1 = make_float2(0.5f*(zf.x + zr.x),  0.5f*(zf.y - zr.y));
        float2 U2 = make_float2(0.5f*(zf.y + zr.y), -0.5f*(zf.x - zr.x));
        float2 Y1 = cmulf(U1, K1[f]);
        float2 Y2 = cmulf(U2, K2[f]);
        Bb[f] = make_float2(Y1.x - Y2.y, Y1.y + Y2.x);
    }
    float2* w = fftN(Bb, A, L2, true);
    float d1 = dvec[h0], d2 = dvec[h0+1];
    float* y1 = g_yT + ((size_t)b*Hd + h0)*Lseq;
    float* y2 = y1 + Lseq;
    for (int l = tid; l < Lseq; l += blockDim.x) {
        float v1 = w[l].x*(1.0f/L2) + u1[l]*d1;
        float v2 = w[l].y*(1.0f/L2) + u2[l]*d2;
        float t1 = 0.7978845608028654f * (v1 + 0.044715f * v1*v1*v1);
        float t2 = 0.7978845608028654f * (v2 + 0.044715f * v2*v2*v2);
        y1[l] = 0.5f * v1 * (1.0f + tanhf(t1));
        y2[l] = 0.5f * v2 * (1.0f + tanhf(t2));
    }
}

// ---------------- gated MLP + residual (transposed weights via DEVICE-SIDE symbol) ----------------
__global__ void mlp_kernel(const float* __restrict__ b1, const float* __restrict__ b2,
                           int lay) {
    const float* __restrict__ w1T = g_w1T + lay*Hd*Hd;   // device-side symbol address (valid)
    const float* __restrict__ w2T = g_w2T + lay*Hd*Hd;
    const int R = 16;
    __shared__ ull zs2[Hd][8];   // packed row-pairs: zs2[k][p] = (y[2p], y[2p+1]) for channel k
    int row0 = blockIdx.x * R;
    int b = row0 >> 11, l0 = row0 & 2047;
    int c = threadIdx.x;   // 128 threads = output channel
    for (int idx = c; idx < Hd*8; idx += 128) {
        int k = idx >> 3, p = idx & 7;
        float2 v = *(const float2*)&g_yT[((size_t)(b*Hd + k))*Lseq + l0 + 2*p];  // gelu'd
        zs2[k][p] = pk(v.x, v.y);
    }
    __syncthreads();
    ull acc1[8], acc2[8];
    {
        float b1v = b1[c], b2v = b2[c];
        ull p1 = pk(b1v, b1v), p2 = pk(b2v, b2v);
        #pragma unroll
        for (int p = 0; p < 8; p++) { acc1[p] = p1; acc2[p] = p2; }
    }
    #pragma unroll 2
    for (int k = 0; k < Hd; k++) {
        float w1v = w1T[k*Hd + c];
        float w2v = w2T[k*Hd + c];
        ull w1p = pk(w1v, w1v), w2p = pk(w2v, w2v);
        #pragma unroll
        for (int p = 0; p < 8; p++) {
            ull zp = zs2[k][p];
            acc1[p] = ffma2(zp, w1p, acc1[p]);
            acc2[p] = ffma2(zp, w2p, acc2[p]);
        }
    }
    #pragma unroll
    for (int p = 0; p < 8; p++) {
        float o0, o1, g0, g1;
        upk(acc1[p], o0, o1);
        upk(acc2[p], g0, g1);
        float r0v = o0 / (1.0f + __expf(-g0));
        float r1v = o1 / (1.0f + __expf(-g1));
        size_t i0 = (size_t)(row0 + 2*p)*Hd + c;
        size_t i1 = (size_t)(row0 + 2*p + 1)*Hd + c;
        g_h[i0] = g_h[i0] + r0v;
        g_h[i1] = g_h[i1] + r1v;
    }
}

// ---------------- decoder (transposed weights) ----------------
__global__ void dec_kernel(const float* __restrict__ bias, float* __restrict__ out) {
    const int R = 32;
    __shared__ float hs[R][Hd];
    int row0 = blockIdx.x * R;
    for (int idx = threadIdx.x; idx < R*Hd; idx += 128)
        hs[idx >> 7][idx & 127] = g_h[(size_t)(row0 + (idx>>7))*Hd + (idx & 127)];
    __syncthreads();
    int o = threadIdx.x & 63;
    int r0 = (threadIdx.x >> 6) * 16;
    float acc[16];
    float bv = bias[o];
    #pragma unroll
    for (int r = 0; r < 16; r++) acc[r] = bv;
    for (int k = 0; k < Hd; k++) {
        float wv = g_decWT[k*OUTF + o];
        #pragma unroll
        for (int r = 0; r < 16; r++) acc[r] = fmaf(hs[r0+r][k], wv, acc[r]);
    }
    #pragma unroll
    for (int r = 0; r < 16; r++)
        out[(size_t)(row0 + r0 + r)*OUTF + o] = acc[r];
}

// ---------------- launch ----------------
extern "C" void kernel_launch(void* const* d_in, const int* in_sizes, int n_in,
                              void* d_out, int out_size) {
    const float* x       = (const float*)d_in[0];
    const float* enc_w   = (const float*)d_in[2];
    const float* enc_b   = (const float*)d_in[3];
    const float* dec_w   = (const float*)d_in[4];
    const float* dec_b   = (const float*)d_in[5];
    const float* lam_re  = (const float*)d_in[6];
    const float* lam_im  = (const float*)d_in[7];
    const float* p_re    = (const float*)d_in[8];
    const float* p_im    = (const float*)d_in[9];
    const float* b_re    = (const float*)d_in[10];
    const float* b_im    = (const float*)d_in[11];
    const float* c_re    = (const float*)d_in[12];
    const float* c_im    = (const float*)d_in[13];
    const float* dvec    = (const float*)d_in[14];
    const float* logstep = (const float*)d_in[15];
    const float* norm_w  = (const float*)d_in[16];
    const float* norm_b  = (const float*)d_in[17];
    const float* w1      = (const float*)d_in[18];
    const float* b1      = (const float*)d_in[19];
    const float* w2      = (const float*)d_in[20];
    const float* b2      = (const float*)d_in[21];
    float* out = (float*)d_out;

    int smem_conv = 2 * L2   * (int)sizeof(float2);  // 64 KB
    int smem_kfft = 2 * Lseq * (int)sizeof(float2);  // 32 KB
    cudaFuncSetAttribute(kfft_kernel, cudaFuncAttributeMaxDynamicSharedMemorySize, smem_kfft);
    cudaFuncSetAttribute(conv_kernel, cudaFuncAttributeMaxDynamicSharedMemorySize, smem_conv);

    twiddle_kernel<<<8, 256>>>();
    prep_kernel<<<(NLAY*Hd*Hd + 255)/256, 256>>>(enc_w, dec_w, w1, w2);
    encoder_kernel<<<ROWS/16, 128>>>(x, enc_b);
    for (int i = 0; i < NLAY; i++) {
        ln_t_kernel<<<ROWS/32, 256>>>(norm_w + i*Hd, norm_b + i*Hd);
        cauchy_kernel<<<dim3(Hd,4), 256>>>(lam_re + i*Hd*Nst, lam_im + i*Hd*Nst,
                                           p_re  + i*Hd*Nst, p_im  + i*Hd*Nst,
                                           b_re  + i*Hd*Nst, b_im  + i*Hd*Nst,
                                           c_re  + i*Hd*Nst, c_im  + i*Hd*Nst,
                                           logstep + i*Hd);
        kfft_kernel<<<Hd, 256, smem_kfft>>>();
        conv_kernel<<<Bsz*Hd/2, 256, smem_conv>>>(dvec + i*Hd);
        mlp_kernel<<<ROWS/16, 128>>>(b1 + i*Hd, b2 + i*Hd, i);
    }
    dec_kernel<<<ROWS/32, 128>>>(dec_b, out);
}

// round 7
// speedup vs baseline: 3.2529x; 1.0674x over previous
#include <cuda_runtime.h>
#include <math.h>

#define Bsz 8
#define Lseq 2048
#define INF 64
#define OUTF 64
#define Hd 128
#define Nst 64
#define NLAY 4
#define L2 4096
#define ROWS (Bsz*Lseq)

typedef unsigned long long ull;

// ---------------- persistent scratch ----------------
__device__ float  g_h  [ROWS*Hd];        // activations (B,L,H)
__device__ float  g_hnT[Bsz*Hd*Lseq];    // layernormed, transposed (B,H,L)
__device__ float  g_yT [Bsz*Hd*Lseq];    // gelu(conv output), transposed (B,H,L)
__device__ float2 g_at [Hd*Lseq];        // at_roots (H, L) complex
__device__ float2 g_Kd [Hd*L2];          // kernel spectrum (H, 4096) complex
__device__ float2 g_tw [L2/2];           // twiddles W_4096^m, m < 2048
__device__ float  g_w1T[NLAY*Hd*Hd];     // transposed weights [k][c]
__device__ float  g_w2T[NLAY*Hd*Hd];
__device__ float  g_encWT[INF*Hd];
__device__ float  g_decWT[Hd*OUTF];

__device__ __forceinline__ float2 cmulf(float2 a, float2 b) {
    return make_float2(a.x*b.x - a.y*b.y, a.x*b.y + a.y*b.x);
}
__device__ __forceinline__ float2 caddf(float2 a, float2 b){ return make_float2(a.x+b.x, a.y+b.y); }
__device__ __forceinline__ float2 csubf(float2 a, float2 b){ return make_float2(a.x-b.x, a.y-b.y); }
__device__ __forceinline__ float2 addi(float2 a, float2 d, float sgn) {
    return make_float2(a.x - sgn*d.y, a.y + sgn*d.x);
}
// ---- packed f32x2 helpers ----
__device__ __forceinline__ ull pk(float x, float y) {
    ull r; asm("mov.b64 %0, {%1, %2};" : "=l"(r) : "f"(x), "f"(y)); return r;
}
__device__ __forceinline__ void upk(ull p, float& x, float& y) {
    asm("mov.b64 {%0, %1}, %2;" : "=f"(x), "=f"(y) : "l"(p));
}
__device__ __forceinline__ ull ffma2(ull a, ull b, ull c) {
    ull d; asm("fma.rn.f32x2 %0, %1, %2, %3;" : "=l"(d) : "l"(a), "l"(b), "l"(c)); return d;
}

// ---------------- twiddle + weight transpose prep ----------------
__global__ void twiddle_kernel() {
    int m = blockIdx.x * blockDim.x + threadIdx.x;
    if (m < L2/2) {
        float s, c;
        sincospif(-(float)m / 2048.0f, &s, &c);
        g_tw[m] = make_float2(c, s);
    }
}
__global__ void prep_kernel(const float* __restrict__ enc_w, const float* __restrict__ dec_w,
                            const float* __restrict__ w1, const float* __restrict__ w2) {
    int tid = blockIdx.x * 256 + threadIdx.x;
    if (tid < INF*Hd) { int k = tid >> 7, c = tid & 127; g_encWT[tid] = enc_w[c*INF + k]; }
    if (tid < Hd*OUTF) { int k = tid >> 6, o = tid & 63; g_decWT[tid] = dec_w[o*Hd + k]; }
    if (tid < NLAY*Hd*Hd) {
        int lay = tid >> 14, r = tid & 16383, k = r >> 7, c = r & 127;
        g_w1T[tid] = w1[lay*Hd*Hd + c*Hd + k];
        g_w2T[tid] = w2[lay*Hd*Hd + c*Hd + k];
    }
}

// ---------------- radix-4 (mixed final radix-2) Stockham FFT, in-smem ----------------
__device__ float2* fftN(float2* a, float2* b, int n, bool inverse) {
    float2* src = a; float2* dst = b;
    const int q = n >> 2;
    const int nst4 = (n == 4096) ? 6 : 5;
    const float sgnF = inverse ? 1.0f : -1.0f;
    int Ls = 1, mult = 1024;
    for (int t = 0; t < nst4; t++) {
        __syncthreads();
        for (int j = threadIdx.x; j < q; j += blockDim.x) {
            int k = j & (Ls - 1);
            int blk = j >> (2*t);
            float2 u0 = src[j], u1 = src[j+q], u2 = src[j+2*q], u3 = src[j+3*q];
            float2 w1 = g_tw[k * mult];
            if (inverse) w1.y = -w1.y;
            float2 w2 = cmulf(w1, w1);
            float2 w3 = cmulf(w2, w1);
            float2 t1 = cmulf(w1, u1), t2 = cmulf(w2, u2), t3 = cmulf(w3, u3);
            float2 a02 = caddf(u0, t2), s02 = csubf(u0, t2);
            float2 a13 = caddf(t1, t3), s13 = csubf(t1, t3);
            int o = (blk << (2*t + 2)) + k;
            dst[o       ] = caddf(a02, a13);
            dst[o +   Ls] = addi(s02, s13, sgnF);
            dst[o + 2*Ls] = csubf(a02, a13);
            dst[o + 3*Ls] = addi(s02, s13, -sgnF);
        }
        { float2* tmp = src; src = dst; dst = tmp; }
        Ls <<= 2; mult >>= 2;
    }
    if (n == 2048) {
        __syncthreads();
        for (int j = threadIdx.x; j < 1024; j += blockDim.x) {
            float2 u = src[j], v = src[j + 1024];
            float2 w = g_tw[2*j];
            if (inverse) w.y = -w.y;
            float2 tv = cmulf(w, v);
            dst[j]        = caddf(u, tv);
            dst[j + 1024] = csubf(u, tv);
        }
        { float2* tmp = src; src = dst; dst = tmp; }
    }
    __syncthreads();
    return src;
}

// ---------------- encoder: h = x @ enc_w.T + enc_b ----------------
__global__ void encoder_kernel(const float* __restrict__ x,
                               const float* __restrict__ bias) {
    const int R = 16;
    __shared__ float xs[R][INF];
    int row0 = blockIdx.x * R;
    int c = threadIdx.x;  // 128 threads = output channel
    for (int idx = c; idx < R*INF; idx += 128)
        xs[idx / INF][idx % INF] = x[(size_t)(row0 + idx/INF)*INF + (idx % INF)];
    __syncthreads();
    float acc[R];
    float bv = bias[c];
    #pragma unroll
    for (int r = 0; r < R; r++) acc[r] = bv;
    for (int k = 0; k < INF; k++) {
        float wv = g_encWT[k*Hd + c];
        #pragma unroll
        for (int r = 0; r < R; r++) acc[r] = fmaf(xs[r][k], wv, acc[r]);
    }
    #pragma unroll
    for (int r = 0; r < R; r++) g_h[(size_t)(row0+r)*Hd + c] = acc[r];
}

// ---------------- layernorm over H, fused transpose -> g_hnT (layer 0 only) ----------------
__global__ void ln_t_kernel(const float* __restrict__ nw, const float* __restrict__ nb) {
    __shared__ float tile[32][129];
    int row0 = blockIdx.x * 32;
    int b = row0 >> 11, l0 = row0 & 2047;
    int warp = threadIdx.x >> 5, lane = threadIdx.x & 31;
    #pragma unroll
    for (int rr = 0; rr < 4; rr++) {
        int l = warp*4 + rr;
        const float* row = g_h + (size_t)(row0 + l)*Hd;
        float v[4]; float sum = 0.f;
        #pragma unroll
        for (int i = 0; i < 4; i++) { v[i] = row[lane + 32*i]; sum += v[i]; }
        #pragma unroll
        for (int o = 16; o; o >>= 1) sum += __shfl_xor_sync(0xffffffffu, sum, o);
        float mu = sum * (1.0f/Hd);
        float var = 0.f;
        #pragma unroll
        for (int i = 0; i < 4; i++) { float t = v[i]-mu; var += t*t; }
        #pragma unroll
        for (int o = 16; o; o >>= 1) var += __shfl_xor_sync(0xffffffffu, var, o);
        var *= (1.0f/Hd);
        float rstd = rsqrtf(var + 1e-5f);
        #pragma unroll
        for (int i = 0; i < 4; i++) {
            int c = lane + 32*i;
            tile[l][c] = (v[i]-mu)*rstd*nw[c] + nb[c];
        }
    }
    __syncthreads();
    for (int idx = threadIdx.x; idx < 32*Hd; idx += 256) {
        int h = idx >> 5, l = idx & 31;
        g_hnT[((size_t)(b*Hd + h))*Lseq + l0 + l] = tile[l][h];
    }
}

// ---------------- cauchy / woodbury with f32x2 accumulation ----------------
__global__ void cauchy_kernel(const float* __restrict__ lre, const float* __restrict__ lim,
                              const float* __restrict__ pre, const float* __restrict__ pim,
                              const float* __restrict__ bre, const float* __restrict__ bim,
                              const float* __restrict__ cre, const float* __restrict__ cim,
                              const float* __restrict__ lstep) {
    int h = blockIdx.x;
    int l0 = blockIdx.y * 512;
    __shared__ float2 slam[Nst];
    __shared__ ull sp[4][Nst][2];   // per matrix: (vx,vy), (vy,-vx)
    int tid = threadIdx.x;
    if (tid < Nst) {
        int idx = h*Nst + tid;
        slam[tid] = make_float2(lre[idx], lim[idx]);
        float2 P  = make_float2(pre[idx], pim[idx]);
        float2 Bv = make_float2(bre[idx], bim[idx]);
        float2 Cc = make_float2(cre[idx], -cim[idx]);
        float2 Pc = make_float2(P.x, -P.y);
        float2 vm[4];
        vm[0] = cmulf(Cc, Bv); vm[1] = cmulf(Cc, P);
        vm[2] = cmulf(Pc, Bv); vm[3] = cmulf(Pc, P);
        #pragma unroll
        for (int m = 0; m < 4; m++) {
            sp[m][tid][0] = pk(vm[m].x, vm[m].y);
            sp[m][tid][1] = pk(vm[m].y, -vm[m].x);
        }
    }
    __syncthreads();
    float ts = 2.0f / __expf(lstep[h]);
    for (int l = l0 + tid; l < l0 + 512; l += blockDim.x) {
        // XLA-style omega (f32 angle + sincosf; l=L/2 must NOT be exactly -1)
        float ang = -6.2831853071795864f * ((float)l / (float)Lseq);
        float s, c;
        sincosf(ang, &s, &c);
        float dpx = 1.0f + c, dpy = s;
        float dmx = 1.0f - c, dmy = -s;
        float id2 = __fdividef(1.0f, dpx*dpx + dpy*dpy);
        float gx = ts * (dmx*dpx + dmy*dpy) * id2;
        float gy = ts * (dmy*dpx - dmx*dpy) * id2;
        float c2x = 2.0f*dpx*id2, c2y = -2.0f*dpy*id2;
        ull acc[4] = {0ull, 0ull, 0ull, 0ull};   // (kx, ky) pairs
        #pragma unroll 8
        for (int n = 0; n < Nst; n++) {
            float dx = gx - slam[n].x;
            float dy = gy - slam[n].y;
            float inv = __fdividef(1.0f, dx*dx + dy*dy);
            float rx = dx*inv, ryp = dy*inv;     // actual ry = -ryp
            ull rxx = pk(rx, rx), ryy = pk(ryp, ryp);
            #pragma unroll
            for (int m = 0; m < 4; m++)
                acc[m] = ffma2(sp[m][n][0], rxx, ffma2(sp[m][n][1], ryy, acc[m]));
        }
        float k00x,k00y,k01x,k01y,k10x,k10y,k11x,k11y;
        upk(acc[0], k00x, k00y); upk(acc[1], k01x, k01y);
        upk(acc[2], k10x, k10y); upk(acc[3], k11x, k11y);
        float opx = 1.0f + k11x, opy = k11y;
        float oinv = __fdividef(1.0f, opx*opx + opy*opy);
        float wx = k01x*k10x - k01y*k10y;
        float wy = k01x*k10y + k01y*k10x;
        float cx = (wx*opx + wy*opy) * oinv;
        float cy = (wy*opx - wx*opy) * oinv;
        float rx2 = k00x - cx, ry2 = k00y - cy;
        g_at[h*Lseq + l] = make_float2(c2x*rx2 - c2y*ry2, c2x*ry2 + c2y*rx2);
    }
}

// ---------------- Kd (4096 bins) from at_roots via even/odd bin split ----------------
__global__ void kfft_kernel() {
    extern __shared__ float2 sm[];
    float2* A  = sm;
    float2* Bb = sm + Lseq;
    int h = blockIdx.x;
    int tid = threadIdx.x;
    const float2* at = g_at + (size_t)h*Lseq;
    for (int l = tid; l < Lseq; l += blockDim.x) A[l] = at[l];
    float2* r = fftN(A, Bb, Lseq, true);
    for (int m = tid; m < Lseq; m += blockDim.x) {
        float2 am = at[m];
        float2 ar = at[(Lseq - m) & (Lseq-1)];
        g_Kd[(size_t)h*L2 + 2*m] = make_float2(0.5f*(am.x + ar.x), 0.5f*(am.y - ar.y));
        float xr = r[m].x * (1.0f/Lseq);
        float2 w = g_tw[m];
        Bb[m] = make_float2(xr * w.x, xr * w.y);
    }
    float2* r2 = fftN(Bb, A, Lseq, false);
    for (int m = tid; m < Lseq; m += blockDim.x)
        g_Kd[(size_t)h*L2 + 2*m + 1] = r2[m];
}

// ---------------- FFT causal conv (2 real channels packed) + fused gelu ----------------
__global__ void conv_kernel(const float* __restrict__ dvec) {
    extern __shared__ float2 sm[];
    float2* A  = sm;
    float2* Bb = sm + L2;
    int blk = blockIdx.x;
    int b = blk >> 6, hp = blk & 63;
    int h0 = 2*hp;
    int tid = threadIdx.x;
    const float* u1 = g_hnT + ((size_t)b*Hd + h0)*Lseq;
    const float* u2 = u1 + Lseq;
    for (int l = tid; l < L2; l += blockDim.x)
        A[l] = (l < Lseq) ? make_float2(u1[l], u2[l]) : make_float2(0.f, 0.f);
    float2* Z = fftN(A, Bb, L2, false);
    const float2* K1 = g_Kd + (size_t)h0*L2;
    const float2* K2 = K1 + L2;
    for (int f = tid; f < L2; f += blockDim.x) {
        int fr = (L2 - f) & (L2-1);
        float2 zf = Z[f], zr = Z[fr];
        float2 U1 = make_float2(0.5f*(zf.x + zr.x),  0.5f*(zf.y - zr.y));
        float2 U2 = make_float2(0.5f*(zf.y + zr.y), -0.5f*(zf.x - zr.x));
        float2 Y1 = cmulf(U1, K1[f]);
        float2 Y2 = cmulf(U2, K2[f]);
        Bb[f] = make_float2(Y1.x - Y2.y, Y1.y + Y2.x);
    }
    float2* w = fftN(Bb, A, L2, true);
    float d1 = dvec[h0], d2 = dvec[h0+1];
    float* y1 = g_yT + ((size_t)b*Hd + h0)*Lseq;
    float* y2 = y1 + Lseq;
    for (int l = tid; l < Lseq; l += blockDim.x) {
        float v1 = w[l].x*(1.0f/L2) + u1[l]*d1;
        float v2 = w[l].y*(1.0f/L2) + u2[l]*d2;
        float t1 = 0.7978845608028654f * (v1 + 0.044715f * v1*v1*v1);
        float t2 = 0.7978845608028654f * (v2 + 0.044715f * v2*v2*v2);
        y1[l] = 0.5f * v1 * (1.0f + tanhf(t1));
        y2[l] = 0.5f * v2 * (1.0f + tanhf(t2));
    }
}

// ---------------- gated MLP + residual + fused next-layer LN ----------------
// 256 threads, 32 rows/block. c = tid&127, half = tid>>7 owns 8 row-pairs.
__global__ __launch_bounds__(256) void mlp_kernel(const float* __restrict__ b1,
                                                  const float* __restrict__ b2,
                                                  const float* __restrict__ nw,
                                                  const float* __restrict__ nb,
                                                  int lay, int do_ln) {
    const float* __restrict__ w1T = g_w1T + lay*Hd*Hd;   // device-side symbol address
    const float* __restrict__ w2T = g_w2T + lay*Hd*Hd;
    __shared__ ull zs2[Hd][16];      // packed row-pairs: zs2[k][p] = (y[2p], y[2p+1])
    __shared__ float tile[32][129];  // residual h rows for LN phase
    int row0 = blockIdx.x * 32;
    int b = row0 >> 11, l0 = row0 & 2047;
    int tid = threadIdx.x;
    int c = tid & 127, half = tid >> 7;
    for (int idx = tid; idx < Hd*16; idx += 256) {
        int k = idx >> 4, p = idx & 15;
        float2 v = *(const float2*)&g_yT[((size_t)(b*Hd + k))*Lseq + l0 + 2*p];  // gelu'd
        zs2[k][p] = pk(v.x, v.y);
    }
    __syncthreads();
    int p0 = half * 8;
    ull acc1[8], acc2[8];
    {
        float b1v = b1[c], b2v = b2[c];
        ull p1 = pk(b1v, b1v), p2 = pk(b2v, b2v);
        #pragma unroll
        for (int p = 0; p < 8; p++) { acc1[p] = p1; acc2[p] = p2; }
    }
    #pragma unroll 2
    for (int k = 0; k < Hd; k++) {
        float w1v = w1T[k*Hd + c];
        float w2v = w2T[k*Hd + c];
        ull w1p = pk(w1v, w1v), w2p = pk(w2v, w2v);
        #pragma unroll
        for (int p = 0; p < 8; p++) {
            ull zp = zs2[k][p0 + p];
            acc1[p] = ffma2(zp, w1p, acc1[p]);
            acc2[p] = ffma2(zp, w2p, acc2[p]);
        }
    }
    #pragma unroll
    for (int p = 0; p < 8; p++) {
        float o0, o1, g0, g1;
        upk(acc1[p], o0, o1);
        upk(acc2[p], g0, g1);
        int ra = 2*(p0 + p), rb = ra + 1;
        size_t ia = (size_t)(row0 + ra)*Hd + c;
        size_t ib = (size_t)(row0 + rb)*Hd + c;
        float ha = g_h[ia] + o0 / (1.0f + __expf(-g0));
        float hb = g_h[ib] + o1 / (1.0f + __expf(-g1));
        g_h[ia] = ha; g_h[ib] = hb;
        tile[ra][c] = ha; tile[rb][c] = hb;
    }
    if (do_ln) {
        __syncthreads();
        int warp = tid >> 5, lane = tid & 31;
        #pragma unroll
        for (int rr = 0; rr < 4; rr++) {
            int l = warp*4 + rr;
            float v[4]; float sum = 0.f;
            #pragma unroll
            for (int i = 0; i < 4; i++) { v[i] = tile[l][lane + 32*i]; sum += v[i]; }
            #pragma unroll
            for (int o = 16; o; o >>= 1) sum += __shfl_xor_sync(0xffffffffu, sum, o);
            float mu = sum * (1.0f/Hd);
            float var = 0.f;
            #pragma unroll
            for (int i = 0; i < 4; i++) { float t = v[i]-mu; var += t*t; }
            #pragma unroll
            for (int o = 16; o; o >>= 1) var += __shfl_xor_sync(0xffffffffu, var, o);
            float rstd = rsqrtf(var * (1.0f/Hd) + 1e-5f);
            #pragma unroll
            for (int i = 0; i < 4; i++) {
                int cc = lane + 32*i;
                tile[l][cc] = (v[i]-mu)*rstd*nw[cc] + nb[cc];
            }
        }
        __syncthreads();
        for (int idx = tid; idx < 32*Hd; idx += 256) {
            int hh = idx >> 5, l = idx & 31;
            g_hnT[((size_t)(b*Hd + hh))*Lseq + l0 + l] = tile[l][hh];
        }
    }
}

// ---------------- decoder (transposed weights) ----------------
__global__ void dec_kernel(const float* __restrict__ bias, float* __restrict__ out) {
    const int R = 32;
    __shared__ float hs[R][Hd];
    int row0 = blockIdx.x * R;
    for (int idx = threadIdx.x; idx < R*Hd; idx += 128)
        hs[idx >> 7][idx & 127] = g_h[(size_t)(row0 + (idx>>7))*Hd + (idx & 127)];
    __syncthreads();
    int o = threadIdx.x & 63;
    int r0 = (threadIdx.x >> 6) * 16;
    float acc[16];
    float bv = bias[o];
    #pragma unroll
    for (int r = 0; r < 16; r++) acc[r] = bv;
    for (int k = 0; k < Hd; k++) {
        float wv = g_decWT[k*OUTF + o];
        #pragma unroll
        for (int r = 0; r < 16; r++) acc[r] = fmaf(hs[r0+r][k], wv, acc[r]);
    }
    #pragma unroll
    for (int r = 0; r < 16; r++)
        out[(size_t)(row0 + r0 + r)*OUTF + o] = acc[r];
}

// ---------------- launch ----------------
extern "C" void kernel_launch(void* const* d_in, const int* in_sizes, int n_in,
                              void* d_out, int out_size) {
    const float* x       = (const float*)d_in[0];
    const float* enc_w   = (const float*)d_in[2];
    const float* enc_b   = (const float*)d_in[3];
    const float* dec_w   = (const float*)d_in[4];
    const float* dec_b   = (const float*)d_in[5];
    const float* lam_re  = (const float*)d_in[6];
    const float* lam_im  = (const float*)d_in[7];
    const float* p_re    = (const float*)d_in[8];
    const float* p_im    = (const float*)d_in[9];
    const float* b_re    = (const float*)d_in[10];
    const float* b_im    = (const float*)d_in[11];
    const float* c_re    = (const float*)d_in[12];
    const float* c_im    = (const float*)d_in[13];
    const float* dvec    = (const float*)d_in[14];
    const float* logstep = (const float*)d_in[15];
    const float* norm_w  = (const float*)d_in[16];
    const float* norm_b  = (const float*)d_in[17];
    const float* w1      = (const float*)d_in[18];
    const float* b1      = (const float*)d_in[19];
    const float* w2      = (const float*)d_in[20];
    const float* b2      = (const float*)d_in[21];
    float* out = (float*)d_out;

    int smem_conv = 2 * L2   * (int)sizeof(float2);  // 64 KB
    int smem_kfft = 2 * Lseq * (int)sizeof(float2);  // 32 KB
    cudaFuncSetAttribute(kfft_kernel, cudaFuncAttributeMaxDynamicSharedMemorySize, smem_kfft);
    cudaFuncSetAttribute(conv_kernel, cudaFuncAttributeMaxDynamicSharedMemorySize, smem_conv);

    twiddle_kernel<<<8, 256>>>();
    prep_kernel<<<(NLAY*Hd*Hd + 255)/256, 256>>>(enc_w, dec_w, w1, w2);
    encoder_kernel<<<ROWS/16, 128>>>(x, enc_b);
    ln_t_kernel<<<ROWS/32, 256>>>(norm_w, norm_b);   // layer-0 LN; later LNs fused in mlp
    for (int i = 0; i < NLAY; i++) {
        cauchy_kernel<<<dim3(Hd,4), 256>>>(lam_re + i*Hd*Nst, lam_im + i*Hd*Nst,
                                           p_re  + i*Hd*Nst, p_im  + i*Hd*Nst,
                                           b_re  + i*Hd*Nst, b_im  + i*Hd*Nst,
                                           c_re  + i*Hd*Nst, c_im  + i*Hd*Nst,
                                           logstep + i*Hd);
        kfft_kernel<<<Hd, 512, smem_kfft>>>();
        conv_kernel<<<Bsz*Hd/2, 512, smem_conv>>>(dvec + i*Hd);
        int last = (i == NLAY-1);
        mlp_kernel<<<ROWS/32, 256>>>(b1 + i*Hd, b2 + i*Hd,
                                     norm_w + (last ? 0 : (i+1)*Hd),
                                     norm_b + (last ? 0 : (i+1)*Hd),
                                     i, last ? 0 : 1);
    }
    dec_kernel<<<ROWS/32, 128>>>(dec_b, out);
}

// round 8
// speedup vs baseline: 3.3636x; 1.0340x over previous
#include <cuda_runtime.h>
#include <math.h>

#define Bsz 8
#define Lseq 2048
#define INF 64
#define OUTF 64
#define Hd 128
#define Nst 64
#define NLAY 4
#define L2 4096
#define ROWS (Bsz*Lseq)

typedef unsigned long long ull;

// ---------------- persistent scratch ----------------
__device__ float  g_h  [ROWS*Hd];        // activations (B,L,H)
__device__ float  g_hnT[Bsz*Hd*Lseq];    // layernormed, transposed (B,H,L)
__device__ float  g_yT [Bsz*Hd*Lseq];    // gelu(conv output), transposed (B,H,L)
__device__ float2 g_at [Hd*Lseq];        // at_roots (H, L) complex
__device__ float2 g_Kd [Hd*L2];          // kernel spectrum (H, 4096) complex
__device__ float2 g_tw [L2/2];           // twiddles W_4096^m, m < 2048
__device__ float  g_w1T[NLAY*Hd*Hd];     // transposed weights [k][c]
__device__ float  g_w2T[NLAY*Hd*Hd];
__device__ float  g_encWT[INF*Hd];
__device__ float  g_decWT[Hd*OUTF];

__device__ __forceinline__ float2 cmulf(float2 a, float2 b) {
    return make_float2(a.x*b.x - a.y*b.y, a.x*b.y + a.y*b.x);
}
__device__ __forceinline__ float2 caddf(float2 a, float2 b){ return make_float2(a.x+b.x, a.y+b.y); }
__device__ __forceinline__ float2 csubf(float2 a, float2 b){ return make_float2(a.x-b.x, a.y-b.y); }
// a + sgn*i*d
__device__ __forceinline__ float2 addi(float2 a, float2 d, float sgn) {
    return make_float2(a.x - sgn*d.y, a.y + sgn*d.x);
}
// ---- packed f32x2 helpers ----
__device__ __forceinline__ ull pk(float x, float y) {
    ull r; asm("mov.b64 %0, {%1, %2};" : "=l"(r) : "f"(x), "f"(y)); return r;
}
__device__ __forceinline__ void upk(ull p, float& x, float& y) {
    asm("mov.b64 {%0, %1}, %2;" : "=f"(x), "=f"(y) : "l"(p));
}
__device__ __forceinline__ ull ffma2(ull a, ull b, ull c) {
    ull d; asm("fma.rn.f32x2 %0, %1, %2, %3;" : "=l"(d) : "l"(a), "l"(b), "l"(c)); return d;
}

// ---------------- twiddle + weight transpose prep ----------------
__global__ void twiddle_kernel() {
    int m = blockIdx.x * blockDim.x + threadIdx.x;
    if (m < L2/2) {
        float s, c;
        sincospif(-(float)m / 2048.0f, &s, &c);
        g_tw[m] = make_float2(c, s);
    }
}
__global__ void prep_kernel(const float* __restrict__ enc_w, const float* __restrict__ dec_w,
                            const float* __restrict__ w1, const float* __restrict__ w2) {
    int tid = blockIdx.x * 256 + threadIdx.x;
    if (tid < INF*Hd) { int k = tid >> 7, c = tid & 127; g_encWT[tid] = enc_w[c*INF + k]; }
    if (tid < Hd*OUTF) { int k = tid >> 6, o = tid & 63; g_decWT[tid] = dec_w[o*Hd + k]; }
    if (tid < NLAY*Hd*Hd) {
        int lay = tid >> 14, r = tid & 16383, k = r >> 7, c = r & 127;
        g_w1T[tid] = w1[lay*Hd*Hd + c*Hd + k];
        g_w2T[tid] = w2[lay*Hd*Hd + c*Hd + k];
    }
}

// ---------------- radix-8 butterfly (DIT-style: twiddles applied to inputs) ----------------
// Forward: sgnF=-1 (W8 = e^{-i pi/4}); inverse: sgnF=+1 and w1..w4 pre-conjugated.
__device__ __forceinline__ void radix8(const float2 u[8],
                                       float2 w1, float2 w2, float2 w3, float2 w4,
                                       float sgnF, float2 out[8]) {
    const float cc = 0.70710678118654752f;
    float2 w5 = cmulf(w4, w1);
    float2 w6 = cmulf(w3, w3);
    float2 w7 = cmulf(w4, w3);
    float2 t0 = u[0];
    float2 t1 = cmulf(w1, u[1]);
    float2 t2 = cmulf(w2, u[2]);
    float2 t3 = cmulf(w3, u[3]);
    float2 t4 = cmulf(w4, u[4]);
    float2 t5 = cmulf(w5, u[5]);
    float2 t6 = cmulf(w6, u[6]);
    float2 t7 = cmulf(w7, u[7]);
    float2 s04 = caddf(t0, t4), d04 = csubf(t0, t4);
    float2 s26 = caddf(t2, t6), d26 = csubf(t2, t6);
    float2 s15 = caddf(t1, t5), d15 = csubf(t1, t5);
    float2 s37 = caddf(t3, t7), d37 = csubf(t3, t7);
    float2 E0 = caddf(s04, s26), E2 = csubf(s04, s26);
    float2 E1 = addi(d04, d26, sgnF), E3 = addi(d04, d26, -sgnF);
    float2 O0 = caddf(s15, s37), O2 = csubf(s15, s37);
    float2 O1 = addi(d15, d37, sgnF), O3 = addi(d15, d37, -sgnF);
    float2 W81 = make_float2(cc,  sgnF*cc);
    float2 W83 = make_float2(-cc, sgnF*cc);
    float2 p1 = cmulf(O1, W81);
    float2 p2 = make_float2(-sgnF*O2.y, sgnF*O2.x);   // sgnF * i * O2
    float2 p3 = cmulf(O3, W83);
    out[0] = caddf(E0, O0); out[4] = csubf(E0, O0);
    out[1] = caddf(E1, p1); out[5] = csubf(E1, p1);
    out[2] = caddf(E2, p2); out[6] = csubf(E2, p2);
    out[3] = caddf(E3, p3); out[7] = csubf(E3, p3);
}

// ---------------- 4096-pt Stockham FFT, 4 radix-8 stages (result in `a`) ----------------
__device__ float2* fft4096_r8(float2* a, float2* b, bool inverse) {
    float2* src = a; float2* dst = b;
    const float sgnF = inverse ? 1.0f : -1.0f;
    int L = 1, mult = 512;
    #pragma unroll
    for (int t = 0; t < 4; t++) {
        __syncthreads();
        for (int j = threadIdx.x; j < 512; j += blockDim.x) {
            int k = j & (L - 1);
            int blk = j >> (3*t);
            float2 u[8];
            #pragma unroll
            for (int i = 0; i < 8; i++) u[i] = src[j + i*512];
            int idx = k * mult;                 // W_{8L}^k = W_4096^{idx}; 4*idx <= 2044
            float2 w1 = g_tw[idx], w2 = g_tw[2*idx], w3 = g_tw[3*idx], w4 = g_tw[4*idx];
            if (inverse) { w1.y = -w1.y; w2.y = -w2.y; w3.y = -w3.y; w4.y = -w4.y; }
            float2 o8[8];
            radix8(u, w1, w2, w3, w4, sgnF, o8);
            int o = (blk << (3*t + 3)) + k;
            #pragma unroll
            for (int i = 0; i < 8; i++) dst[o + i*L] = o8[i];
        }
        { float2* tmp = src; src = dst; dst = tmp; }
        L <<= 3; mult >>= 3;
    }
    __syncthreads();
    return src;   // 4 stages -> back in `a`
}

// ---------------- 2048-pt Stockham FFT: radix-4 then 3x radix-8 (result in `a`) ----------------
__device__ float2* fft2048_m(float2* a, float2* b, bool inverse) {
    float2* src = a; float2* dst = b;
    const float sgnF = inverse ? 1.0f : -1.0f;
    // stage 0: radix-4, L=1 (no twiddles)
    __syncthreads();
    for (int j = threadIdx.x; j < 512; j += blockDim.x) {
        float2 u0 = src[j], u1 = src[j+512], u2 = src[j+1024], u3 = src[j+1536];
        float2 a02 = caddf(u0, u2), s02 = csubf(u0, u2);
        float2 a13 = caddf(u1, u3), s13 = csubf(u1, u3);
        int o = j << 2;
        dst[o  ] = caddf(a02, a13);
        dst[o+1] = addi(s02, s13, sgnF);
        dst[o+2] = csubf(a02, a13);
        dst[o+3] = addi(s02, s13, -sgnF);
    }
    { float2* tmp = src; src = dst; dst = tmp; }
    // stages 1..3: radix-8 with L = 4, 32, 256; W_{8L}^k = W_4096^{k*mult}
    int L = 4, mult = 128;
    #pragma unroll
    for (int t = 0; t < 3; t++) {
        __syncthreads();
        for (int j = threadIdx.x; j < 256; j += blockDim.x) {
            int k = j & (L - 1);
            int blk = j >> (2 + 3*t);
            float2 u[8];
            #pragma unroll
            for (int i = 0; i < 8; i++) u[i] = src[j + i*256];
            int idx = k * mult;                 // 4*idx <= 2040
            float2 w1 = g_tw[idx], w2 = g_tw[2*idx], w3 = g_tw[3*idx], w4 = g_tw[4*idx];
            if (inverse) { w1.y = -w1.y; w2.y = -w2.y; w3.y = -w3.y; w4.y = -w4.y; }
            float2 o8[8];
            radix8(u, w1, w2, w3, w4, sgnF, o8);
            int o = (blk << 3)*L + k;
            #pragma unroll
            for (int i = 0; i < 8; i++) dst[o + i*L] = o8[i];
        }
        { float2* tmp = src; src = dst; dst = tmp; }
        L <<= 3; mult >>= 3;
    }
    __syncthreads();
    return src;   // 4 stages -> back in `a`
}

// ---------------- encoder: h = x @ enc_w.T + enc_b ----------------
__global__ void encoder_kernel(const float* __restrict__ x,
                               const float* __restrict__ bias) {
    const int R = 16;
    __shared__ float xs[R][INF];
    int row0 = blockIdx.x * R;
    int c = threadIdx.x;  // 128 threads = output channel
    for (int idx = c; idx < R*INF; idx += 128)
        xs[idx / INF][idx % INF] = x[(size_t)(row0 + idx/INF)*INF + (idx % INF)];
    __syncthreads();
    float acc[R];
    float bv = bias[c];
    #pragma unroll
    for (int r = 0; r < R; r++) acc[r] = bv;
    for (int k = 0; k < INF; k++) {
        float wv = g_encWT[k*Hd + c];
        #pragma unroll
        for (int r = 0; r < R; r++) acc[r] = fmaf(xs[r][k], wv, acc[r]);
    }
    #pragma unroll
    for (int r = 0; r < R; r++) g_h[(size_t)(row0+r)*Hd + c] = acc[r];
}

// ---------------- layernorm over H, fused transpose -> g_hnT (layer 0 only) ----------------
__global__ void ln_t_kernel(const float* __restrict__ nw, const float* __restrict__ nb) {
    __shared__ float tile[32][129];
    int row0 = blockIdx.x * 32;
    int b = row0 >> 11, l0 = row0 & 2047;
    int warp = threadIdx.x >> 5, lane = threadIdx.x & 31;
    #pragma unroll
    for (int rr = 0; rr < 4; rr++) {
        int l = warp*4 + rr;
        const float* row = g_h + (size_t)(row0 + l)*Hd;
        float v[4]; float sum = 0.f;
        #pragma unroll
        for (int i = 0; i < 4; i++) { v[i] = row[lane + 32*i]; sum += v[i]; }
        #pragma unroll
        for (int o = 16; o; o >>= 1) sum += __shfl_xor_sync(0xffffffffu, sum, o);
        float mu = sum * (1.0f/Hd);
        float var = 0.f;
        #pragma unroll
        for (int i = 0; i < 4; i++) { float t = v[i]-mu; var += t*t; }
        #pragma unroll
        for (int o = 16; o; o >>= 1) var += __shfl_xor_sync(0xffffffffu, var, o);
        var *= (1.0f/Hd);
        float rstd = rsqrtf(var + 1e-5f);
        #pragma unroll
        for (int i = 0; i < 4; i++) {
            int c = lane + 32*i;
            tile[l][c] = (v[i]-mu)*rstd*nw[c] + nb[c];
        }
    }
    __syncthreads();
    for (int idx = threadIdx.x; idx < 32*Hd; idx += 256) {
        int h = idx >> 5, l = idx & 31;
        g_hnT[((size_t)(b*Hd + h))*Lseq + l0 + l] = tile[l][h];
    }
}

// ---------------- cauchy / woodbury with f32x2 accumulation ----------------
__global__ void cauchy_kernel(const float* __restrict__ lre, const float* __restrict__ lim,
                              const float* __restrict__ pre, const float* __restrict__ pim,
                              const float* __restrict__ bre, const float* __restrict__ bim,
                              const float* __restrict__ cre, const float* __restrict__ cim,
                              const float* __restrict__ lstep) {
    int h = blockIdx.x;
    int l0 = blockIdx.y * 512;
    __shared__ float2 slam[Nst];
    __shared__ ull sp[4][Nst][2];   // per matrix: (vx,vy), (vy,-vx)
    int tid = threadIdx.x;
    if (tid < Nst) {
        int idx = h*Nst + tid;
        slam[tid] = make_float2(lre[idx], lim[idx]);
        float2 P  = make_float2(pre[idx], pim[idx]);
        float2 Bv = make_float2(bre[idx], bim[idx]);
        float2 Cc = make_float2(cre[idx], -cim[idx]);
        float2 Pc = make_float2(P.x, -P.y);
        float2 vm[4];
        vm[0] = cmulf(Cc, Bv); vm[1] = cmulf(Cc, P);
        vm[2] = cmulf(Pc, Bv); vm[3] = cmulf(Pc, P);
        #pragma unroll
        for (int m = 0; m < 4; m++) {
            sp[m][tid][0] = pk(vm[m].x, vm[m].y);
            sp[m][tid][1] = pk(vm[m].y, -vm[m].x);
        }
    }
    __syncthreads();
    float ts = 2.0f / __expf(lstep[h]);
    for (int l = l0 + tid; l < l0 + 512; l += blockDim.x) {
        // XLA-style omega (f32 angle + sincosf; l=L/2 must NOT be exactly -1)
        float ang = -6.2831853071795864f * ((float)l / (float)Lseq);
        float s, c;
        sincosf(ang, &s, &c);
        float dpx = 1.0f + c, dpy = s;
        float dmx = 1.0f - c, dmy = -s;
        float id2 = __fdividef(1.0f, dpx*dpx + dpy*dpy);
        float gx = ts * (dmx*dpx + dmy*dpy) * id2;
        float gy = ts * (dmy*dpx - dmx*dpy) * id2;
        float c2x = 2.0f*dpx*id2, c2y = -2.0f*dpy*id2;
        ull acc[4] = {0ull, 0ull, 0ull, 0ull};   // (kx, ky) pairs
        #pragma unroll 8
        for (int n = 0; n < Nst; n++) {
            float dx = gx - slam[n].x;
            float dy = gy - slam[n].y;
            float inv = __fdividef(1.0f, dx*dx + dy*dy);
            float rx = dx*inv, ryp = dy*inv;     // actual ry = -ryp
            ull rxx = pk(rx, rx), ryy = pk(ryp, ryp);
            #pragma unroll
            for (int m = 0; m < 4; m++)
                acc[m] = ffma2(sp[m][n][0], rxx, ffma2(sp[m][n][1], ryy, acc[m]));
        }
        float k00x,k00y,k01x,k01y,k10x,k10y,k11x,k11y;
        upk(acc[0], k00x, k00y); upk(acc[1], k01x, k01y);
        upk(acc[2], k10x, k10y); upk(acc[3], k11x, k11y);
        float opx = 1.0f + k11x, opy = k11y;
        float oinv = __fdividef(1.0f, opx*opx + opy*opy);
        float wx = k01x*k10x - k01y*k10y;
        float wy = k01x*k10y + k01y*k10x;
        float cx = (wx*opx + wy*opy) * oinv;
        float cy = (wy*opx - wx*opy) * oinv;
        float rx2 = k00x - cx, ry2 = k00y - cy;
        g_at[h*Lseq + l] = make_float2(c2x*rx2 - c2y*ry2, c2x*ry2 + c2y*rx2);
    }
}

// ---------------- Kd (4096 bins) from at_roots via even/odd bin split ----------------
__global__ void kfft_kernel() {
    extern __shared__ float2 sm[];
    float2* A  = sm;
    float2* Bb = sm + Lseq;
    int h = blockIdx.x;
    int tid = threadIdx.x;
    const float2* at = g_at + (size_t)h*Lseq;
    for (int l = tid; l < Lseq; l += blockDim.x) A[l] = at[l];
    float2* r = fft2048_m(A, Bb, true);
    for (int m = tid; m < Lseq; m += blockDim.x) {
        float2 am = at[m];
        float2 ar = at[(Lseq - m) & (Lseq-1)];
        g_Kd[(size_t)h*L2 + 2*m] = make_float2(0.5f*(am.x + ar.x), 0.5f*(am.y - ar.y));
        float xr = r[m].x * (1.0f/Lseq);
        float2 w = g_tw[m];
        Bb[m] = make_float2(xr * w.x, xr * w.y);
    }
    float2* r2 = fft2048_m(Bb, A, false);
    for (int m = tid; m < Lseq; m += blockDim.x)
        g_Kd[(size_t)h*L2 + 2*m + 1] = r2[m];
}

// ---------------- FFT causal conv (2 real channels packed) + fused gelu ----------------
__global__ void conv_kernel(const float* __restrict__ dvec) {
    extern __shared__ float2 sm[];
    float2* A  = sm;
    float2* Bb = sm + L2;
    int blk = blockIdx.x;
    int b = blk >> 6, hp = blk & 63;
    int h0 = 2*hp;
    int tid = threadIdx.x;
    const float* u1 = g_hnT + ((size_t)b*Hd + h0)*Lseq;
    const float* u2 = u1 + Lseq;
    for (int l = tid; l < L2; l += blockDim.x)
        A[l] = (l < Lseq) ? make_float2(u1[l], u2[l]) : make_float2(0.f, 0.f);
    float2* Z = fft4096_r8(A, Bb, false);
    const float2* K1 = g_Kd + (size_t)h0*L2;
    const float2* K2 = K1 + L2;
    for (int f = tid; f < L2; f += blockDim.x) {
        int fr = (L2 - f) & (L2-1);
        float2 zf = Z[f], zr = Z[fr];
        float2 U1 = make_float2(0.5f*(zf.x + zr.x),  0.5f*(zf.y - zr.y));
        float2 U2 = make_float2(0.5f*(zf.y + zr.y), -0.5f*(zf.x - zr.x));
        float2 Y1 = cmulf(U1, K1[f]);
        float2 Y2 = cmulf(U2, K2[f]);
        Bb[f] = make_float2(Y1.x - Y2.y, Y1.y + Y2.x);
    }
    float2* w = fft4096_r8(Bb, A, true);
    float d1 = dvec[h0], d2 = dvec[h0+1];
    float* y1 = g_yT + ((size_t)b*Hd + h0)*Lseq;
    float* y2 = y1 + Lseq;
    for (int l = tid; l < Lseq; l += blockDim.x) {
        float v1 = w[l].x*(1.0f/L2) + u1[l]*d1;
        float v2 = w[l].y*(1.0f/L2) + u2[l]*d2;
        float t1 = 0.7978845608028654f * (v1 + 0.044715f * v1*v1*v1);
        float t2 = 0.7978845608028654f * (v2 + 0.044715f * v2*v2*v2);
        y1[l] = 0.5f * v1 * (1.0f + tanhf(t1));
        y2[l] = 0.5f * v2 * (1.0f + tanhf(t2));
    }
}

// ---------------- gated MLP + residual + fused next-layer LN ----------------
__global__ __launch_bounds__(256) void mlp_kernel(const float* __restrict__ b1,
                                                  const float* __restrict__ b2,
                                                  const float* __restrict__ nw,
                                                  const float* __restrict__ nb,
                                                  int lay, int do_ln) {
    const float* __restrict__ w1T = g_w1T + lay*Hd*Hd;   // device-side symbol address
    const float* __restrict__ w2T = g_w2T + lay*Hd*Hd;
    __shared__ ull zs2[Hd][16];      // packed row-pairs: zs2[k][p] = (y[2p], y[2p+1])
    __shared__ float tile[32][129];  // residual h rows for LN phase
    int row0 = blockIdx.x * 32;
    int b = row0 >> 11, l0 = row0 & 2047;
    int tid = threadIdx.x;
    int c = tid & 127, half = tid >> 7;
    for (int idx = tid; idx < Hd*16; idx += 256) {
        int k = idx >> 4, p = idx & 15;
        float2 v = *(const float2*)&g_yT[((size_t)(b*Hd + k))*Lseq + l0 + 2*p];  // gelu'd
        zs2[k][p] = pk(v.x, v.y);
    }
    __syncthreads();
    int p0 = half * 8;
    ull acc1[8], acc2[8];
    {
        float b1v = b1[c], b2v = b2[c];
        ull p1 = pk(b1v, b1v), p2 = pk(b2v, b2v);
        #pragma unroll
        for (int p = 0; p < 8; p++) { acc1[p] = p1; acc2[p] = p2; }
    }
    #pragma unroll 2
    for (int k = 0; k < Hd; k++) {
        float w1v = w1T[k*Hd + c];
        float w2v = w2T[k*Hd + c];
        ull w1p = pk(w1v, w1v), w2p = pk(w2v, w2v);
        #pragma unroll
        for (int p = 0; p < 8; p++) {
            ull zp = zs2[k][p0 + p];
            acc1[p] = ffma2(zp, w1p, acc1[p]);
            acc2[p] = ffma2(zp, w2p, acc2[p]);
        }
    }
    #pragma unroll
    for (int p = 0; p < 8; p++) {
        float o0, o1, g0, g1;
        upk(acc1[p], o0, o1);
        upk(acc2[p], g0, g1);
        int ra = 2*(p0 + p), rb = ra + 1;
        size_t ia = (size_t)(row0 + ra)*Hd + c;
        size_t ib = (size_t)(row0 + rb)*Hd + c;
        float ha = g_h[ia] + o0 / (1.0f + __expf(-g0));
        float hb = g_h[ib] + o1 / (1.0f + __expf(-g1));
        g_h[ia] = ha; g_h[ib] = hb;
        tile[ra][c] = ha; tile[rb][c] = hb;
    }
    if (do_ln) {
        __syncthreads();
        int warp = tid >> 5, lane = tid & 31;
        #pragma unroll
        for (int rr = 0; rr < 4; rr++) {
            int l = warp*4 + rr;
            float v[4]; float sum = 0.f;
            #pragma unroll
            for (int i = 0; i < 4; i++) { v[i] = tile[l][lane + 32*i]; sum += v[i]; }
            #pragma unroll
            for (int o = 16; o; o >>= 1) sum += __shfl_xor_sync(0xffffffffu, sum, o);
            float mu = sum * (1.0f/Hd);
            float var = 0.f;
            #pragma unroll
            for (int i = 0; i < 4; i++) { float t = v[i]-mu; var += t*t; }
            #pragma unroll
            for (int o = 16; o; o >>= 1) var += __shfl_xor_sync(0xffffffffu, var, o);
            float rstd = rsqrtf(var * (1.0f/Hd) + 1e-5f);
            #pragma unroll
            for (int i = 0; i < 4; i++) {
                int cc = lane + 32*i;
                tile[l][cc] = (v[i]-mu)*rstd*nw[cc] + nb[cc];
            }
        }
        __syncthreads();
        for (int idx = tid; idx < 32*Hd; idx += 256) {
            int hh = idx >> 5, l = idx & 31;
            g_hnT[((size_t)(b*Hd + hh))*Lseq + l0 + l] = tile[l][hh];
        }
    }
}

// ---------------- decoder (transposed weights) ----------------
__global__ void dec_kernel(const float* __restrict__ bias, float* __restrict__ out) {
    const int R = 32;
    __shared__ float hs[R][Hd];
    int row0 = blockIdx.x * R;
    for (int idx = threadIdx.x; idx < R*Hd; idx += 128)
        hs[idx >> 7][idx & 127] = g_h[(size_t)(row0 + (idx>>7))*Hd + (idx & 127)];
    __syncthreads();
    int o = threadIdx.x & 63;
    int r0 = (threadIdx.x >> 6) * 16;
    float acc[16];
    float bv = bias[o];
    #pragma unroll
    for (int r = 0; r < 16; r++) acc[r] = bv;
    for (int k = 0; k < Hd; k++) {
        float wv = g_decWT[k*OUTF + o];
        #pragma unroll
        for (int r = 0; r < 16; r++) acc[r] = fmaf(hs[r0+r][k], wv, acc[r]);
    }
    #pragma unroll
    for (int r = 0; r < 16; r++)
        out[(size_t)(row0 + r0 + r)*OUTF + o] = acc[r];
}

// ---------------- launch ----------------
extern "C" void kernel_launch(void* const* d_in, const int* in_sizes, int n_in,
                              void* d_out, int out_size) {
    const float* x       = (const float*)d_in[0];
    const float* enc_w   = (const float*)d_in[2];
    const float* enc_b   = (const float*)d_in[3];
    const float* dec_w   = (const float*)d_in[4];
    const float* dec_b   = (const float*)d_in[5];
    const float* lam_re  = (const float*)d_in[6];
    const float* lam_im  = (const float*)d_in[7];
    const float* p_re    = (const float*)d_in[8];
    const float* p_im    = (const float*)d_in[9];
    const float* b_re    = (const float*)d_in[10];
    const float* b_im    = (const float*)d_in[11];
    const float* c_re    = (const float*)d_in[12];
    const float* c_im    = (const float*)d_in[13];
    const float* dvec    = (const float*)d_in[14];
    const float* logstep = (const float*)d_in[15];
    const float* norm_w  = (const float*)d_in[16];
    const float* norm_b  = (const float*)d_in[17];
    const float* w1      = (const float*)d_in[18];
    const float* b1      = (const float*)d_in[19];
    const float* w2      = (const float*)d_in[20];
    const float* b2      = (const float*)d_in[21];
    float* out = (float*)d_out;

    int smem_conv = 2 * L2   * (int)sizeof(float2);  // 64 KB
    int smem_kfft = 2 * Lseq * (int)sizeof(float2);  // 32 KB
    cudaFuncSetAttribute(kfft_kernel, cudaFuncAttributeMaxDynamicSharedMemorySize, smem_kfft);
    cudaFuncSetAttribute(conv_kernel, cudaFuncAttributeMaxDynamicSharedMemorySize, smem_conv);

    twiddle_kernel<<<8, 256>>>();
    prep_kernel<<<(NLAY*Hd*Hd + 255)/256, 256>>>(enc_w, dec_w, w1, w2);
    encoder_kernel<<<ROWS/16, 128>>>(x, enc_b);
    ln_t_kernel<<<ROWS/32, 256>>>(norm_w, norm_b);   // layer-0 LN; later LNs fused in mlp
    for (int i = 0; i < NLAY; i++) {
        cauchy_kernel<<<dim3(Hd,4), 256>>>(lam_re + i*Hd*Nst, lam_im + i*Hd*Nst,
                                           p_re  + i*Hd*Nst, p_im  + i*Hd*Nst,
                                           b_re  + i*Hd*Nst, b_im  + i*Hd*Nst,
                                           c_re  + i*Hd*Nst, c_im  + i*Hd*Nst,
                                           logstep + i*Hd);
        kfft_kernel<<<Hd, 256, smem_kfft>>>();
        conv_kernel<<<Bsz*Hd/2, 512, smem_conv>>>(dvec + i*Hd);
        int last = (i == NLAY-1);
        mlp_kernel<<<ROWS/32, 256>>>(b1 + i*Hd, b2 + i*Hd,
                                     norm_w + (last ? 0 : (i+1)*Hd),
                                     norm_b + (last ? 0 : (i+1)*Hd),
                                     i, last ? 0 : 1);
    }
    dec_kernel<<<ROWS/32, 128>>>(dec_b, out);
}

// round 9
// speedup vs baseline: 3.5984x; 1.0698x over previous
#include <cuda_runtime.h>
#include <math.h>

#define Bsz 8
#define Lseq 2048
#define INF 64
#define OUTF 64
#define Hd 128
#define Nst 64
#define NLAY 4
#define L2 4096
#define ROWS (Bsz*Lseq)

typedef unsigned long long ull;

// ---------------- persistent scratch ----------------
__device__ float  g_h  [ROWS*Hd];        // activations (B,L,H)
__device__ float  g_hnT[Bsz*Hd*Lseq];    // layernormed, transposed (B,H,L)
__device__ float  g_yT [Bsz*Hd*Lseq];    // gelu(conv output), transposed (B,H,L)
__device__ float2 g_Kd [NLAY*Hd*L2];     // kernel spectra, all layers (lay,H,4096)
__device__ float2 g_tw [L2/2];           // twiddles W_4096^m, m < 2048
__device__ float  g_w1T[NLAY*Hd*Hd];     // transposed weights [k][c]
__device__ float  g_w2T[NLAY*Hd*Hd];
__device__ float  g_encWT[INF*Hd];
__device__ float  g_decWT[Hd*OUTF];

__device__ __forceinline__ float2 cmulf(float2 a, float2 b) {
    return make_float2(a.x*b.x - a.y*b.y, a.x*b.y + a.y*b.x);
}
__device__ __forceinline__ float2 caddf(float2 a, float2 b){ return make_float2(a.x+b.x, a.y+b.y); }
__device__ __forceinline__ float2 csubf(float2 a, float2 b){ return make_float2(a.x-b.x, a.y-b.y); }
// a + sgn*i*d
__device__ __forceinline__ float2 addi(float2 a, float2 d, float sgn) {
    return make_float2(a.x - sgn*d.y, a.y + sgn*d.x);
}
// ---- packed f32x2 helpers ----
__device__ __forceinline__ ull pk(float x, float y) {
    ull r; asm("mov.b64 %0, {%1, %2};" : "=l"(r) : "f"(x), "f"(y)); return r;
}
__device__ __forceinline__ void upk(ull p, float& x, float& y) {
    asm("mov.b64 {%0, %1}, %2;" : "=f"(x), "=f"(y) : "l"(p));
}
__device__ __forceinline__ ull ffma2(ull a, ull b, ull c) {
    ull d; asm("fma.rn.f32x2 %0, %1, %2, %3;" : "=l"(d) : "l"(a), "l"(b), "l"(c)); return d;
}

// ---------------- twiddle + weight transpose prep ----------------
__global__ void twiddle_kernel() {
    int m = blockIdx.x * blockDim.x + threadIdx.x;
    if (m < L2/2) {
        float s, c;
        sincospif(-(float)m / 2048.0f, &s, &c);
        g_tw[m] = make_float2(c, s);
    }
}
__global__ void prep_kernel(const float* __restrict__ enc_w, const float* __restrict__ dec_w,
                            const float* __restrict__ w1, const float* __restrict__ w2) {
    int tid = blockIdx.x * 256 + threadIdx.x;
    if (tid < INF*Hd) { int k = tid >> 7, c = tid & 127; g_encWT[tid] = enc_w[c*INF + k]; }
    if (tid < Hd*OUTF) { int k = tid >> 6, o = tid & 63; g_decWT[tid] = dec_w[o*Hd + k]; }
    if (tid < NLAY*Hd*Hd) {
        int lay = tid >> 14, r = tid & 16383, k = r >> 7, c = r & 127;
        g_w1T[tid] = w1[lay*Hd*Hd + c*Hd + k];
        g_w2T[tid] = w2[lay*Hd*Hd + c*Hd + k];
    }
}

// ---------------- radix-8 butterfly (DIT-style: twiddles applied to inputs) ----------------
__device__ __forceinline__ void radix8(const float2 u[8],
                                       float2 w1, float2 w2, float2 w3, float2 w4,
                                       float sgnF, float2 out[8]) {
    const float cc = 0.70710678118654752f;
    float2 w5 = cmulf(w4, w1);
    float2 w6 = cmulf(w3, w3);
    float2 w7 = cmulf(w4, w3);
    float2 t0 = u[0];
    float2 t1 = cmulf(w1, u[1]);
    float2 t2 = cmulf(w2, u[2]);
    float2 t3 = cmulf(w3, u[3]);
    float2 t4 = cmulf(w4, u[4]);
    float2 t5 = cmulf(w5, u[5]);
    float2 t6 = cmulf(w6, u[6]);
    float2 t7 = cmulf(w7, u[7]);
    float2 s04 = caddf(t0, t4), d04 = csubf(t0, t4);
    float2 s26 = caddf(t2, t6), d26 = csubf(t2, t6);
    float2 s15 = caddf(t1, t5), d15 = csubf(t1, t5);
    float2 s37 = caddf(t3, t7), d37 = csubf(t3, t7);
    float2 E0 = caddf(s04, s26), E2 = csubf(s04, s26);
    float2 E1 = addi(d04, d26, sgnF), E3 = addi(d04, d26, -sgnF);
    float2 O0 = caddf(s15, s37), O2 = csubf(s15, s37);
    float2 O1 = addi(d15, d37, sgnF), O3 = addi(d15, d37, -sgnF);
    float2 W81 = make_float2(cc,  sgnF*cc);
    float2 W83 = make_float2(-cc, sgnF*cc);
    float2 p1 = cmulf(O1, W81);
    float2 p2 = make_float2(-sgnF*O2.y, sgnF*O2.x);   // sgnF * i * O2
    float2 p3 = cmulf(O3, W83);
    out[0] = caddf(E0, O0); out[4] = csubf(E0, O0);
    out[1] = caddf(E1, p1); out[5] = csubf(E1, p1);
    out[2] = caddf(E2, p2); out[6] = csubf(E2, p2);
    out[3] = caddf(E3, p3); out[7] = csubf(E3, p3);
}

// ---------------- 4096-pt Stockham FFT, 4 radix-8 stages (result in `a`) ----------------
__device__ float2* fft4096_r8(float2* a, float2* b, bool inverse) {
    float2* src = a; float2* dst = b;
    const float sgnF = inverse ? 1.0f : -1.0f;
    int L = 1, mult = 512;
    #pragma unroll
    for (int t = 0; t < 4; t++) {
        __syncthreads();
        for (int j = threadIdx.x; j < 512; j += blockDim.x) {
            int k = j & (L - 1);
            int blk = j >> (3*t);
            float2 u[8];
            #pragma unroll
            for (int i = 0; i < 8; i++) u[i] = src[j + i*512];
            int idx = k * mult;
            float2 w1 = g_tw[idx], w2 = g_tw[2*idx], w3 = g_tw[3*idx], w4 = g_tw[4*idx];
            if (inverse) { w1.y = -w1.y; w2.y = -w2.y; w3.y = -w3.y; w4.y = -w4.y; }
            float2 o8[8];
            radix8(u, w1, w2, w3, w4, sgnF, o8);
            int o = (blk << (3*t + 3)) + k;
            #pragma unroll
            for (int i = 0; i < 8; i++) dst[o + i*L] = o8[i];
        }
        { float2* tmp = src; src = dst; dst = tmp; }
        L <<= 3; mult >>= 3;
    }
    __syncthreads();
    return src;   // 4 stages -> back in `a`
}

// ---------------- 2048-pt Stockham FFT: radix-4 then 3x radix-8 (result in `a`) ----------------
__device__ float2* fft2048_m(float2* a, float2* b, bool inverse) {
    float2* src = a; float2* dst = b;
    const float sgnF = inverse ? 1.0f : -1.0f;
    // stage 0: radix-4, L=1 (no twiddles)
    __syncthreads();
    for (int j = threadIdx.x; j < 512; j += blockDim.x) {
        float2 u0 = src[j], u1 = src[j+512], u2 = src[j+1024], u3 = src[j+1536];
        float2 a02 = caddf(u0, u2), s02 = csubf(u0, u2);
        float2 a13 = caddf(u1, u3), s13 = csubf(u1, u3);
        int o = j << 2;
        dst[o  ] = caddf(a02, a13);
        dst[o+1] = addi(s02, s13, sgnF);
        dst[o+2] = csubf(a02, a13);
        dst[o+3] = addi(s02, s13, -sgnF);
    }
    { float2* tmp = src; src = dst; dst = tmp; }
    // stages 1..3: radix-8 with L = 4, 32, 256; W_{8L}^k = W_4096^{k*mult}
    int L = 4, mult = 128;
    #pragma unroll
    for (int t = 0; t < 3; t++) {
        __syncthreads();
        for (int j = threadIdx.x; j < 256; j += blockDim.x) {
            int k = j & (L - 1);
            int blk = j >> (2 + 3*t);
            float2 u[8];
            #pragma unroll
            for (int i = 0; i < 8; i++) u[i] = src[j + i*256];
            int idx = k * mult;
            float2 w1 = g_tw[idx], w2 = g_tw[2*idx], w3 = g_tw[3*idx], w4 = g_tw[4*idx];
            if (inverse) { w1.y = -w1.y; w2.y = -w2.y; w3.y = -w3.y; w4.y = -w4.y; }
            float2 o8[8];
            radix8(u, w1, w2, w3, w4, sgnF, o8);
            int o = (blk << 3)*L + k;
            #pragma unroll
            for (int i = 0; i < 8; i++) dst[o + i*L] = o8[i];
        }
        { float2* tmp = src; src = dst; dst = tmp; }
        L <<= 3; mult >>= 3;
    }
    __syncthreads();
    return src;   // 4 stages -> back in `a`
}

// ---------------- encoder: h = x @ enc_w.T + enc_b ----------------
__global__ void encoder_kernel(const float* __restrict__ x,
                               const float* __restrict__ bias) {
    const int R = 16;
    __shared__ float xs[R][INF];
    int row0 = blockIdx.x * R;
    int c = threadIdx.x;  // 128 threads = output channel
    for (int idx = c; idx < R*INF; idx += 128)
        xs[idx / INF][idx % INF] = x[(size_t)(row0 + idx/INF)*INF + (idx % INF)];
    __syncthreads();
    float acc[R];
    float bv = bias[c];
    #pragma unroll
    for (int r = 0; r < R; r++) acc[r] = bv;
    for (int k = 0; k < INF; k++) {
        float wv = g_encWT[k*Hd + c];
        #pragma unroll
        for (int r = 0; r < R; r++) acc[r] = fmaf(xs[r][k], wv, acc[r]);
    }
    #pragma unroll
    for (int r = 0; r < R; r++) g_h[(size_t)(row0+r)*Hd + c] = acc[r];
}

// ---------------- layernorm over H, fused transpose -> g_hnT (layer 0 only) ----------------
__global__ void ln_t_kernel(const float* __restrict__ nw, const float* __restrict__ nb) {
    __shared__ float tile[32][129];
    int row0 = blockIdx.x * 32;
    int b = row0 >> 11, l0 = row0 & 2047;
    int warp = threadIdx.x >> 5, lane = threadIdx.x & 31;
    #pragma unroll
    for (int rr = 0; rr < 4; rr++) {
        int l = warp*4 + rr;
        const float* row = g_h + (size_t)(row0 + l)*Hd;
        float v[4]; float sum = 0.f;
        #pragma unroll
        for (int i = 0; i < 4; i++) { v[i] = row[lane + 32*i]; sum += v[i]; }
        #pragma unroll
        for (int o = 16; o; o >>= 1) sum += __shfl_xor_sync(0xffffffffu, sum, o);
        float mu = sum * (1.0f/Hd);
        float var = 0.f;
        #pragma unroll
        for (int i = 0; i < 4; i++) { float t = v[i]-mu; var += t*t; }
        #pragma unroll
        for (int o = 16; o; o >>= 1) var += __shfl_xor_sync(0xffffffffu, var, o);
        var *= (1.0f/Hd);
        float rstd = rsqrtf(var + 1e-5f);
        #pragma unroll
        for (int i = 0; i < 4; i++) {
            int c = lane + 32*i;
            tile[l][c] = (v[i]-mu)*rstd*nw[c] + nb[c];
        }
    }
    __syncthreads();
    for (int idx = threadIdx.x; idx < 32*Hd; idx += 256) {
        int h = idx >> 5, l = idx & 31;
        g_hnT[((size_t)(b*Hd + h))*Lseq + l0 + l] = tile[l][h];
    }
}

// ---------------- FUSED cauchy + kernel-spectrum, batched over layers ----------------
// grid (Hd, NLAY), 512 threads. Computes at_roots directly in smem, writes even Kd
// bins before the in-place IFFT, then the odd bins via a second 2048 FFT.
__global__ __launch_bounds__(512) void ckfft_kernel(
        const float* __restrict__ lre, const float* __restrict__ lim,
        const float* __restrict__ pre, const float* __restrict__ pim,
        const float* __restrict__ bre, const float* __restrict__ bim,
        const float* __restrict__ cre, const float* __restrict__ cim,
        const float* __restrict__ lstep) {
    extern __shared__ float2 sm[];
    float2* A  = sm;           // 2048
    float2* Bb = sm + Lseq;    // 2048
    __shared__ float2 slam[Nst];
    __shared__ ull sp[4][Nst][2];
    int h = blockIdx.x, lay = blockIdx.y;
    int hh = lay*Hd + h;
    int tid = threadIdx.x;
    if (tid < Nst) {
        int idx = hh*Nst + tid;
        slam[tid] = make_float2(lre[idx], lim[idx]);
        float2 P  = make_float2(pre[idx], pim[idx]);
        float2 Bv = make_float2(bre[idx], bim[idx]);
        float2 Cc = make_float2(cre[idx], -cim[idx]);
        float2 Pc = make_float2(P.x, -P.y);
        float2 vm[4];
        vm[0] = cmulf(Cc, Bv); vm[1] = cmulf(Cc, P);
        vm[2] = cmulf(Pc, Bv); vm[3] = cmulf(Pc, P);
        #pragma unroll
        for (int m = 0; m < 4; m++) {
            sp[m][tid][0] = pk(vm[m].x, vm[m].y);
            sp[m][tid][1] = pk(vm[m].y, -vm[m].x);
        }
    }
    __syncthreads();
    float ts = 2.0f / __expf(lstep[hh]);
    for (int l = tid; l < Lseq; l += 512) {
        // XLA-style omega (f32 angle + sincosf; l=L/2 must NOT be exactly -1)
        float ang = -6.2831853071795864f * ((float)l / (float)Lseq);
        float s, c;
        sincosf(ang, &s, &c);
        float dpx = 1.0f + c, dpy = s;
        float dmx = 1.0f - c, dmy = -s;
        float id2 = __fdividef(1.0f, dpx*dpx + dpy*dpy);
        float gx = ts * (dmx*dpx + dmy*dpy) * id2;
        float gy = ts * (dmy*dpx - dmx*dpy) * id2;
        float c2x = 2.0f*dpx*id2, c2y = -2.0f*dpy*id2;
        ull acc[4] = {0ull, 0ull, 0ull, 0ull};
        #pragma unroll 8
        for (int n = 0; n < Nst; n++) {
            float dx = gx - slam[n].x;
            float dy = gy - slam[n].y;
            float inv = __fdividef(1.0f, dx*dx + dy*dy);
            float rx = dx*inv, ryp = dy*inv;
            ull rxx = pk(rx, rx), ryy = pk(ryp, ryp);
            #pragma unroll
            for (int m = 0; m < 4; m++)
                acc[m] = ffma2(sp[m][n][0], rxx, ffma2(sp[m][n][1], ryy, acc[m]));
        }
        float k00x,k00y,k01x,k01y,k10x,k10y,k11x,k11y;
        upk(acc[0], k00x, k00y); upk(acc[1], k01x, k01y);
        upk(acc[2], k10x, k10y); upk(acc[3], k11x, k11y);
        float opx = 1.0f + k11x, opy = k11y;
        float oinv = __fdividef(1.0f, opx*opx + opy*opy);
        float wx = k01x*k10x - k01y*k10y;
        float wy = k01x*k10y + k01y*k10x;
        float cx = (wx*opx + wy*opy) * oinv;
        float cy = (wy*opx - wx*opy) * oinv;
        float rx2 = k00x - cx, ry2 = k00y - cy;
        A[l] = make_float2(c2x*rx2 - c2y*ry2, c2x*ry2 + c2y*rx2);
    }
    __syncthreads();
    float2* Kd = g_Kd + (size_t)hh*L2;
    // even bins from at (A) BEFORE the in-place IFFT destroys it
    for (int m = tid; m < Lseq; m += 512) {
        float2 am = A[m];
        float2 ar = A[(Lseq - m) & (Lseq-1)];
        Kd[2*m] = make_float2(0.5f*(am.x + ar.x), 0.5f*(am.y - ar.y));
    }
    // NOTE: no sync needed here beyond the one inside fft2048_m's first stage
    float2* r = fft2048_m(A, Bb, true);   // unnormalized inverse; result in A
    for (int m = tid; m < Lseq; m += 512) {
        float xr = r[m].x * (1.0f/Lseq);
        float2 w = g_tw[m];
        Bb[m] = make_float2(xr * w.x, xr * w.y);
    }
    float2* r2 = fft2048_m(Bb, A, false); // result in Bb
    for (int m = tid; m < Lseq; m += 512)
        Kd[2*m + 1] = r2[m];
}

// ---------------- FFT causal conv (2 real channels packed) + fused gelu ----------------
__global__ void conv_kernel(const float* __restrict__ dvec, int lay) {
    extern __shared__ float2 sm[];
    float2* A  = sm;
    float2* Bb = sm + L2;
    int blk = blockIdx.x;
    int b = blk >> 6, hp = blk & 63;
    int h0 = 2*hp;
    int tid = threadIdx.x;
    const float* u1 = g_hnT + ((size_t)b*Hd + h0)*Lseq;
    const float* u2 = u1 + Lseq;
    for (int l = tid; l < L2; l += blockDim.x)
        A[l] = (l < Lseq) ? make_float2(u1[l], u2[l]) : make_float2(0.f, 0.f);
    float2* Z = fft4096_r8(A, Bb, false);
    const float2* K1 = g_Kd + ((size_t)lay*Hd + h0)*L2;
    const float2* K2 = K1 + L2;
    for (int f = tid; f < L2; f += blockDim.x) {
        int fr = (L2 - f) & (L2-1);
        float2 zf = Z[f], zr = Z[fr];
        float2 U1 = make_float2(0.5f*(zf.x + zr.x),  0.5f*(zf.y - zr.y));
        float2 U2 = make_float2(0.5f*(zf.y + zr.y), -0.5f*(zf.x - zr.x));
        float2 Y1 = cmulf(U1, K1[f]);
        float2 Y2 = cmulf(U2, K2[f]);
        Bb[f] = make_float2(Y1.x - Y2.y, Y1.y + Y2.x);
    }
    float2* w = fft4096_r8(Bb, A, true);
    float d1 = dvec[h0], d2 = dvec[h0+1];
    float* y1 = g_yT + ((size_t)b*Hd + h0)*Lseq;
    float* y2 = y1 + Lseq;
    for (int l = tid; l < Lseq; l += blockDim.x) {
        float v1 = w[l].x*(1.0f/L2) + u1[l]*d1;
        float v2 = w[l].y*(1.0f/L2) + u2[l]*d2;
        float t1 = 0.7978845608028654f * (v1 + 0.044715f * v1*v1*v1);
        float t2 = 0.7978845608028654f * (v2 + 0.044715f * v2*v2*v2);
        y1[l] = 0.5f * v1 * (1.0f + tanhf(t1));
        y2[l] = 0.5f * v2 * (1.0f + tanhf(t2));
    }
}

// ---------------- gated MLP + residual + fused next-layer LN ----------------
__global__ __launch_bounds__(256) void mlp_kernel(const float* __restrict__ b1,
                                                  const float* __restrict__ b2,
                                                  const float* __restrict__ nw,
                                                  const float* __restrict__ nb,
                                                  int lay, int do_ln) {
    const float* __restrict__ w1T = g_w1T + lay*Hd*Hd;
    const float* __restrict__ w2T = g_w2T + lay*Hd*Hd;
    __shared__ ull zs2[Hd][16];
    __shared__ float tile[32][129];
    int row0 = blockIdx.x * 32;
    int b = row0 >> 11, l0 = row0 & 2047;
    int tid = threadIdx.x;
    int c = tid & 127, half = tid >> 7;
    for (int idx = tid; idx < Hd*16; idx += 256) {
        int k = idx >> 4, p = idx & 15;
        float2 v = *(const float2*)&g_yT[((size_t)(b*Hd + k))*Lseq + l0 + 2*p];
        zs2[k][p] = pk(v.x, v.y);
    }
    __syncthreads();
    int p0 = half * 8;
    ull acc1[8], acc2[8];
    {
        float b1v = b1[c], b2v = b2[c];
        ull p1 = pk(b1v, b1v), p2 = pk(b2v, b2v);
        #pragma unroll
        for (int p = 0; p < 8; p++) { acc1[p] = p1; acc2[p] = p2; }
    }
    #pragma unroll 2
    for (int k = 0; k < Hd; k++) {
        float w1v = w1T[k*Hd + c];
        float w2v = w2T[k*Hd + c];
        ull w1p = pk(w1v, w1v), w2p = pk(w2v, w2v);
        #pragma unroll
        for (int p = 0; p < 8; p++) {
            ull zp = zs2[k][p0 + p];
            acc1[p] = ffma2(zp, w1p, acc1[p]);
            acc2[p] = ffma2(zp, w2p, acc2[p]);
        }
    }
    #pragma unroll
    for (int p = 0; p < 8; p++) {
        float o0, o1, g0, g1;
        upk(acc1[p], o0, o1);
        upk(acc2[p], g0, g1);
        int ra = 2*(p0 + p), rb = ra + 1;
        size_t ia = (size_t)(row0 + ra)*Hd + c;
        size_t ib = (size_t)(row0 + rb)*Hd + c;
        float ha = g_h[ia] + o0 / (1.0f + __expf(-g0));
        float hb = g_h[ib] + o1 / (1.0f + __expf(-g1));
        g_h[ia] = ha; g_h[ib] = hb;
        tile[ra][c] = ha; tile[rb][c] = hb;
    }
    if (do_ln) {
        __syncthreads();
        int warp = tid >> 5, lane = tid & 31;
        #pragma unroll
        for (int rr = 0; rr < 4; rr++) {
            int l = warp*4 + rr;
            float v[4]; float sum = 0.f;
            #pragma unroll
            for (int i = 0; i < 4; i++) { v[i] = tile[l][lane + 32*i]; sum += v[i]; }
            #pragma unroll
            for (int o = 16; o; o >>= 1) sum += __shfl_xor_sync(0xffffffffu, sum, o);
            float mu = sum * (1.0f/Hd);
            float var = 0.f;
            #pragma unroll
            for (int i = 0; i < 4; i++) { float t = v[i]-mu; var += t*t; }
            #pragma unroll
            for (int o = 16; o; o >>= 1) var += __shfl_xor_sync(0xffffffffu, var, o);
            float rstd = rsqrtf(var * (1.0f/Hd) + 1e-5f);
            #pragma unroll
            for (int i = 0; i < 4; i++) {
                int cc = lane + 32*i;
                tile[l][cc] = (v[i]-mu)*rstd*nw[cc] + nb[cc];
            }
        }
        __syncthreads();
        for (int idx = tid; idx < 32*Hd; idx += 256) {
            int hh = idx >> 5, l = idx & 31;
            g_hnT[((size_t)(b*Hd + hh))*Lseq + l0 + l] = tile[l][hh];
        }
    }
}

// ---------------- decoder (transposed weights) ----------------
__global__ void dec_kernel(const float* __restrict__ bias, float* __restrict__ out) {
    const int R = 32;
    __shared__ float hs[R][Hd];
    int row0 = blockIdx.x * R;
    for (int idx = threadIdx.x; idx < R*Hd; idx += 128)
        hs[idx >> 7][idx & 127] = g_h[(size_t)(row0 + (idx>>7))*Hd + (idx & 127)];
    __syncthreads();
    int o = threadIdx.x & 63;
    int r0 = (threadIdx.x >> 6) * 16;
    float acc[16];
    float bv = bias[o];
    #pragma unroll
    for (int r = 0; r < 16; r++) acc[r] = bv;
    for (int k = 0; k < Hd; k++) {
        float wv = g_decWT[k*OUTF + o];
        #pragma unroll
        for (int r = 0; r < 16; r++) acc[r] = fmaf(hs[r0+r][k], wv, acc[r]);
    }
    #pragma unroll
    for (int r = 0; r < 16; r++)
        out[(size_t)(row0 + r0 + r)*OUTF + o] = acc[r];
}

// ---------------- launch ----------------
extern "C" void kernel_launch(void* const* d_in, const int* in_sizes, int n_in,
                              void* d_out, int out_size) {
    const float* x       = (const float*)d_in[0];
    const float* enc_w   = (const float*)d_in[2];
    const float* enc_b   = (const float*)d_in[3];
    const float* dec_w   = (const float*)d_in[4];
    const float* dec_b   = (const float*)d_in[5];
    const float* lam_re  = (const float*)d_in[6];
    const float* lam_im  = (const float*)d_in[7];
    const float* p_re    = (const float*)d_in[8];
    const float* p_im    = (const float*)d_in[9];
    const float* b_re    = (const float*)d_in[10];
    const float* b_im    = (const float*)d_in[11];
    const float* c_re    = (const float*)d_in[12];
    const float* c_im    = (const float*)d_in[13];
    const float* dvec    = (const float*)d_in[14];
    const float* logstep = (const float*)d_in[15];
    const float* norm_w  = (const float*)d_in[16];
    const float* norm_b  = (const float*)d_in[17];
    const float* w1      = (const float*)d_in[18];
    const float* b1      = (const float*)d_in[19];
    const float* w2      = (const float*)d_in[20];
    const float* b2      = (const float*)d_in[21];
    float* out = (float*)d_out;

    int smem_conv  = 2 * L2   * (int)sizeof(float2);  // 64 KB
    int smem_ckfft = 2 * Lseq * (int)sizeof(float2);  // 32 KB
    cudaFuncSetAttribute(ckfft_kernel, cudaFuncAttributeMaxDynamicSharedMemorySize, smem_ckfft);
    cudaFuncSetAttribute(conv_kernel, cudaFuncAttributeMaxDynamicSharedMemorySize, smem_conv);

    twiddle_kernel<<<8, 256>>>();
    prep_kernel<<<(NLAY*Hd*Hd + 255)/256, 256>>>(enc_w, dec_w, w1, w2);
    // all 4 layers' kernel spectra upfront (input-independent)
    ckfft_kernel<<<dim3(Hd, NLAY), 512, smem_ckfft>>>(lam_re, lam_im, p_re, p_im,
                                                      b_re, b_im, c_re, c_im, logstep);
    encoder_kernel<<<ROWS/16, 128>>>(x, enc_b);
    ln_t_kernel<<<ROWS/32, 256>>>(norm_w, norm_b);   // layer-0 LN; later LNs fused in mlp
    for (int i = 0; i < NLAY; i++) {
        conv_kernel<<<Bsz*Hd/2, 512, smem_conv>>>(dvec + i*Hd, i);
        int last = (i == NLAY-1);
        mlp_kernel<<<ROWS/32, 256>>>(b1 + i*Hd, b2 + i*Hd,
                                     norm_w + (last ? 0 : (i+1)*Hd),
                                     norm_b + (last ? 0 : (i+1)*Hd),
                                     i, last ? 0 : 1);
    }
    dec_kernel<<<ROWS/32, 128>>>(dec_b, out);
}

// round 11
// speedup vs baseline: 4.0041x; 1.1127x over previous
#include <cuda_runtime.h>
#include <math.h>

#define Bsz 8
#define Lseq 2048
#define INF 64
#define OUTF 64
#define Hd 128
#define Nst 64
#define NLAY 4
#define L2 4096
#define ROWS (Bsz*Lseq)

typedef unsigned long long ull;

// ---------------- persistent scratch ----------------
__device__ float  g_h  [ROWS*Hd];        // activations (B,L,H)
__device__ float  g_hnT[Bsz*Hd*Lseq];    // layernormed, transposed (B,H,L)
__device__ float  g_yT [Bsz*Hd*Lseq];    // gelu(conv output), transposed (B,H,L)
__device__ float2 g_Kd [NLAY*Hd*L2];     // kernel spectra, all layers (lay,H,4096)
__device__ float2 g_tw [L2/2];           // twiddles W_4096^m, m < 2048
__device__ float  g_w1T[NLAY*Hd*Hd];     // transposed weights [k][c]
__device__ float  g_w2T[NLAY*Hd*Hd];
__device__ float  g_encWT[INF*Hd];
__device__ float  g_decWT[Hd*OUTF];

__device__ __forceinline__ float2 cmulf(float2 a, float2 b) {
    return make_float2(a.x*b.x - a.y*b.y, a.x*b.y + a.y*b.x);
}
__device__ __forceinline__ float2 caddf(float2 a, float2 b){ return make_float2(a.x+b.x, a.y+b.y); }
__device__ __forceinline__ float2 csubf(float2 a, float2 b){ return make_float2(a.x-b.x, a.y-b.y); }
// a + sgn*i*d
__device__ __forceinline__ float2 addi(float2 a, float2 d, float sgn) {
    return make_float2(a.x - sgn*d.y, a.y + sgn*d.x);
}
// ---- packed f32x2 helpers ----
__device__ __forceinline__ ull pk(float x, float y) {
    ull r; asm("mov.b64 %0, {%1, %2};" : "=l"(r) : "f"(x), "f"(y)); return r;
}
__device__ __forceinline__ void upk(ull p, float& x, float& y) {
    asm("mov.b64 {%0, %1}, %2;" : "=f"(x), "=f"(y) : "l"(p));
}
__device__ __forceinline__ ull ffma2(ull a, ull b, ull c) {
    ull d; asm("fma.rn.f32x2 %0, %1, %2, %3;" : "=l"(d) : "l"(a), "l"(b), "l"(c)); return d;
}

// ---------------- twiddle + weight transpose prep ----------------
__global__ void twiddle_kernel() {
    int m = blockIdx.x * blockDim.x + threadIdx.x;
    if (m < L2/2) {
        float s, c;
        sincospif(-(float)m / 2048.0f, &s, &c);
        g_tw[m] = make_float2(c, s);
    }
}
__global__ void prep_kernel(const float* __restrict__ enc_w, const float* __restrict__ dec_w,
                            const float* __restrict__ w1, const float* __restrict__ w2) {
    int tid = blockIdx.x * 256 + threadIdx.x;
    if (tid < INF*Hd) { int k = tid >> 7, c = tid & 127; g_encWT[tid] = enc_w[c*INF + k]; }
    if (tid < Hd*OUTF) { int k = tid >> 6, o = tid & 63; g_decWT[tid] = dec_w[o*Hd + k]; }
    if (tid < NLAY*Hd*Hd) {
        int lay = tid >> 14, r = tid & 16383, k = r >> 7, c = r & 127;
        g_w1T[tid] = w1[lay*Hd*Hd + c*Hd + k];
        g_w2T[tid] = w2[lay*Hd*Hd + c*Hd + k];
    }
}

// ---------------- radix-8 butterfly (DIT-style: twiddles applied to inputs) ----------------
__device__ __forceinline__ void radix8(const float2 u[8],
                                       float2 w1, float2 w2, float2 w3, float2 w4,
                                       float sgnF, float2 out[8]) {
    const float cc = 0.70710678118654752f;
    float2 w5 = cmulf(w4, w1);
    float2 w6 = cmulf(w3, w3);
    float2 w7 = cmulf(w4, w3);
    float2 t0 = u[0];
    float2 t1 = cmulf(w1, u[1]);
    float2 t2 = cmulf(w2, u[2]);
    float2 t3 = cmulf(w3, u[3]);
    float2 t4 = cmulf(w4, u[4]);
    float2 t5 = cmulf(w5, u[5]);
    float2 t6 = cmulf(w6, u[6]);
    float2 t7 = cmulf(w7, u[7]);
    float2 s04 = caddf(t0, t4), d04 = csubf(t0, t4);
    float2 s26 = caddf(t2, t6), d26 = csubf(t2, t6);
    float2 s15 = caddf(t1, t5), d15 = csubf(t1, t5);
    float2 s37 = caddf(t3, t7), d37 = csubf(t3, t7);
    float2 E0 = caddf(s04, s26), E2 = csubf(s04, s26);
    float2 E1 = addi(d04, d26, sgnF), E3 = addi(d04, d26, -sgnF);
    float2 O0 = caddf(s15, s37), O2 = csubf(s15, s37);
    float2 O1 = addi(d15, d37, sgnF), O3 = addi(d15, d37, -sgnF);
    float2 W81 = make_float2(cc,  sgnF*cc);
    float2 W83 = make_float2(-cc, sgnF*cc);
    float2 p1 = cmulf(O1, W81);
    float2 p2 = make_float2(-sgnF*O2.y, sgnF*O2.x);   // sgnF * i * O2
    float2 p3 = cmulf(O3, W83);
    out[0] = caddf(E0, O0); out[4] = csubf(E0, O0);
    out[1] = caddf(E1, p1); out[5] = csubf(E1, p1);
    out[2] = caddf(E2, p2); out[6] = csubf(E2, p2);
    out[3] = caddf(E3, p3); out[7] = csubf(E3, p3);
}

// ---------------- 2048-pt Stockham FFT: radix-4 then 3x radix-8 (result in `a`) ----------------
// Double-buffered; used only by ckfft (runs once).
__device__ float2* fft2048_m(float2* a, float2* b, bool inverse) {
    float2* src = a; float2* dst = b;
    const float sgnF = inverse ? 1.0f : -1.0f;
    __syncthreads();
    for (int j = threadIdx.x; j < 512; j += blockDim.x) {
        float2 u0 = src[j], u1 = src[j+512], u2 = src[j+1024], u3 = src[j+1536];
        float2 a02 = caddf(u0, u2), s02 = csubf(u0, u2);
        float2 a13 = caddf(u1, u3), s13 = csubf(u1, u3);
        int o = j << 2;
        dst[o  ] = caddf(a02, a13);
        dst[o+1] = addi(s02, s13, sgnF);
        dst[o+2] = csubf(a02, a13);
        dst[o+3] = addi(s02, s13, -sgnF);
    }
    { float2* tmp = src; src = dst; dst = tmp; }
    int L = 4, mult = 128;
    #pragma unroll
    for (int t = 0; t < 3; t++) {
        __syncthreads();
        for (int j = threadIdx.x; j < 256; j += blockDim.x) {
            int k = j & (L - 1);
            int blk = j >> (2 + 3*t);
            float2 u[8];
            #pragma unroll
            for (int i = 0; i < 8; i++) u[i] = src[j + i*256];
            int idx = k * mult;
            float2 w1 = g_tw[idx], w2 = g_tw[2*idx], w3 = g_tw[3*idx], w4 = g_tw[4*idx];
            if (inverse) { w1.y = -w1.y; w2.y = -w2.y; w3.y = -w3.y; w4.y = -w4.y; }
            float2 o8[8];
            radix8(u, w1, w2, w3, w4, sgnF, o8);
            int o = (blk << 3)*L + k;
            #pragma unroll
            for (int i = 0; i < 8; i++) dst[o + i*L] = o8[i];
        }
        { float2* tmp = src; src = dst; dst = tmp; }
        L <<= 3; mult >>= 3;
    }
    __syncthreads();
    return src;
}

// ---------------- one in-place radix-8 stage (4096 pts, 256 threads, 2 bf/thread) ----------------
// Enter/exit with the block synced. Reads all before writing (barrier in between).
__device__ __forceinline__ void stage_ip(float2* A, int t, int L, int mult,
                                         float sgnF, bool conj) {
    float2 u[2][8];
    #pragma unroll
    for (int q = 0; q < 2; q++) {
        int j = threadIdx.x + q*256;
        #pragma unroll
        for (int i = 0; i < 8; i++) u[q][i] = A[j + i*512];
    }
    __syncthreads();
    #pragma unroll
    for (int q = 0; q < 2; q++) {
        int j = threadIdx.x + q*256;
        int k = j & (L - 1);
        int blkq = j >> (3*t);
        int idx = k * mult;
        float2 w1 = g_tw[idx], w2 = g_tw[2*idx], w3 = g_tw[3*idx], w4 = g_tw[4*idx];
        if (conj) { w1.y = -w1.y; w2.y = -w2.y; w3.y = -w3.y; w4.y = -w4.y; }
        float2 o8[8];
        radix8(u[q], w1, w2, w3, w4, sgnF, o8);
        int o = (blkq << (3*t + 3)) + k;
        #pragma unroll
        for (int i = 0; i < 8; i++) A[o + i*L] = o8[i];
    }
    __syncthreads();
}

// ---------------- FFT causal conv, in-place single-buffer (32 KB), fused ends ----------------
__global__ __launch_bounds__(256, 4) void conv_kernel(const float* __restrict__ dvec, int lay) {
    __shared__ float2 A[L2];
    int blk = blockIdx.x;
    int b = blk >> 6, hp = blk & 63;
    int h0 = 2*hp;
    int tid = threadIdx.x;
    const float* u1 = g_hnT + ((size_t)b*Hd + h0)*Lseq;
    const float* u2 = u1 + Lseq;
    const float2 ONE = make_float2(1.f, 0.f);

    // forward stage 0 (L=1, twiddles=1): global -> butterflies -> A; upper half is zero
    #pragma unroll
    for (int q = 0; q < 2; q++) {
        int j = tid + q*256;
        float2 u[8], o8[8];
        #pragma unroll
        for (int i = 0; i < 4; i++) u[i] = make_float2(u1[j + i*512], u2[j + i*512]);
        #pragma unroll
        for (int i = 4; i < 8; i++) u[i] = make_float2(0.f, 0.f);
        radix8(u, ONE, ONE, ONE, ONE, -1.0f, o8);
        #pragma unroll
        for (int i = 0; i < 8; i++) A[(j << 3) + i] = o8[i];
    }
    __syncthreads();
    // forward stages 1..3
    stage_ip(A, 1, 8,   64, -1.0f, false);
    stage_ip(A, 2, 64,  8,  -1.0f, false);
    stage_ip(A, 3, 512, 1,  -1.0f, false);

    // pointwise, in conjugate PAIRS (f, 4096-f): thread-local read+write covers ALL 4096 bins.
    const float2* K1 = g_Kd + ((size_t)lay*Hd + h0)*L2;
    const float2* K2 = K1 + L2;
    #pragma unroll
    for (int s = 0; s < 8; s++) {
        int f  = tid + s*256;              // 0..2047
        int fr = (L2 - f) & (L2-1);        // {0} or 2049..4095
        float2 zf = A[f], zr = A[fr];
        // Y at f
        {
            float2 U1 = make_float2(0.5f*(zf.x + zr.x),  0.5f*(zf.y - zr.y));
            float2 U2 = make_float2(0.5f*(zf.y + zr.y), -0.5f*(zf.x - zr.x));
            float2 Y1 = cmulf(U1, K1[f]);
            float2 Y2 = cmulf(U2, K2[f]);
            A[f] = make_float2(Y1.x - Y2.y, Y1.y + Y2.x);
        }
        // Y at fr (roles of zf/zr swapped); for f==0 this rewrites A[0] with the same value
        {
            float2 U1 = make_float2(0.5f*(zr.x + zf.x),  0.5f*(zr.y - zf.y));
            float2 U2 = make_float2(0.5f*(zr.y + zf.y), -0.5f*(zr.x - zf.x));
            float2 Y1 = cmulf(U1, K1[fr]);
            float2 Y2 = cmulf(U2, K2[fr]);
            A[fr] = make_float2(Y1.x - Y2.y, Y1.y + Y2.x);
        }
        if (f == 0) {  // self-paired bin 2048 (not covered by any pair above)
            float2 z = A[2048];
            float2 U1 = make_float2(z.x, 0.f);
            float2 U2 = make_float2(z.y, 0.f);
            float2 Y1 = cmulf(U1, K1[2048]);
            float2 Y2 = cmulf(U2, K2[2048]);
            A[2048] = make_float2(Y1.x - Y2.y, Y1.y + Y2.x);
        }
    }
    __syncthreads();

    // inverse stage 0 (L=1, twiddles=1)
    {
        float2 u[2][8];
        #pragma unroll
        for (int q = 0; q < 2; q++) {
            int j = tid + q*256;
            #pragma unroll
            for (int i = 0; i < 8; i++) u[q][i] = A[j + i*512];
        }
        __syncthreads();
        #pragma unroll
        for (int q = 0; q < 2; q++) {
            int j = tid + q*256;
            float2 o8[8];
            radix8(u[q], ONE, ONE, ONE, ONE, 1.0f, o8);
            #pragma unroll
            for (int i = 0; i < 8; i++) A[(j << 3) + i] = o8[i];
        }
        __syncthreads();
    }
    stage_ip(A, 1, 8,  64, 1.0f, true);
    stage_ip(A, 2, 64, 8,  1.0f, true);
    // inverse stage 3 fused with epilogue: keep only l < 2048 (i < 4), write global
    {
        float d1 = dvec[h0], d2 = dvec[h0+1];
        float* y1 = g_yT + ((size_t)b*Hd + h0)*Lseq;
        float* y2 = y1 + Lseq;
        float2 u[2][8];
        #pragma unroll
        for (int q = 0; q < 2; q++) {
            int j = tid + q*256;
            #pragma unroll
            for (int i = 0; i < 8; i++) u[q][i] = A[j + i*512];
        }
        // no smem writes follow -> no barrier needed
        #pragma unroll
        for (int q = 0; q < 2; q++) {
            int j = tid + q*256;          // k = j (L=512), blk = 0
            int idx = j;                   // mult = 1
            float2 w1 = g_tw[idx], w2 = g_tw[2*idx], w3 = g_tw[3*idx], w4 = g_tw[4*idx];
            w1.y = -w1.y; w2.y = -w2.y; w3.y = -w3.y; w4.y = -w4.y;
            float2 o8[8];
            radix8(u[q], w1, w2, w3, w4, 1.0f, o8);
            #pragma unroll
            for (int i = 0; i < 4; i++) {
                int l = j + i*512;
                float v1 = o8[i].x*(1.0f/L2) + u1[l]*d1;
                float v2 = o8[i].y*(1.0f/L2) + u2[l]*d2;
                float t1 = 0.7978845608028654f * (v1 + 0.044715f * v1*v1*v1);
                float t2 = 0.7978845608028654f * (v2 + 0.044715f * v2*v2*v2);
                y1[l] = 0.5f * v1 * (1.0f + tanhf(t1));
                y2[l] = 0.5f * v2 * (1.0f + tanhf(t2));
            }
        }
    }
}

// ---------------- encoder GEMM (f32x2 row-pairs) + fused layer-0 LN -> g_h, g_hnT ----------------
__global__ __launch_bounds__(256) void encoder_kernel(const float* __restrict__ x,
                                                      const float* __restrict__ eb,
                                                      const float* __restrict__ nw,
                                                      const float* __restrict__ nb) {
    __shared__ float xs[32][INF];     // staged input rows
    __shared__ ull   zs2[INF][17];    // packed row-pairs (pad 17 to break bank conflicts)
    __shared__ float tile[32][129];   // h rows for LN
    int row0 = blockIdx.x * 32;
    int b = row0 >> 11, l0 = row0 & 2047;
    int tid = threadIdx.x;
    for (int idx = tid; idx < 32*INF; idx += 256)
        xs[idx >> 6][idx & 63] = x[(size_t)(row0 + (idx >> 6))*INF + (idx & 63)];
    __syncthreads();
    for (int idx = tid; idx < INF*16; idx += 256) {
        int p = idx >> 6, k = idx & 63;
        zs2[k][p] = pk(xs[2*p][k], xs[2*p+1][k]);
    }
    __syncthreads();
    int c = tid & 127, half = tid >> 7;
    int p0 = half * 8;
    ull acc[8];
    {
        float bv = eb[c];
        ull bp = pk(bv, bv);
        #pragma unroll
        for (int p = 0; p < 8; p++) acc[p] = bp;
    }
    #pragma unroll 4
    for (int k = 0; k < INF; k++) {
        float wv = g_encWT[k*Hd + c];
        ull wp = pk(wv, wv);
        #pragma unroll
        for (int p = 0; p < 8; p++) acc[p] = ffma2(zs2[k][p0 + p], wp, acc[p]);
    }
    #pragma unroll
    for (int p = 0; p < 8; p++) {
        float h0v, h1v;
        upk(acc[p], h0v, h1v);
        int ra = 2*(p0 + p), rb = ra + 1;
        g_h[(size_t)(row0 + ra)*Hd + c] = h0v;
        g_h[(size_t)(row0 + rb)*Hd + c] = h1v;
        tile[ra][c] = h0v; tile[rb][c] = h1v;
    }
    __syncthreads();
    int warp = tid >> 5, lane = tid & 31;
    #pragma unroll
    for (int rr = 0; rr < 4; rr++) {
        int l = warp*4 + rr;
        float v[4]; float sum = 0.f;
        #pragma unroll
        for (int i = 0; i < 4; i++) { v[i] = tile[l][lane + 32*i]; sum += v[i]; }
        #pragma unroll
        for (int o = 16; o; o >>= 1) sum += __shfl_xor_sync(0xffffffffu, sum, o);
        float mu = sum * (1.0f/Hd);
        float var = 0.f;
        #pragma unroll
        for (int i = 0; i < 4; i++) { float t = v[i]-mu; var += t*t; }
        #pragma unroll
        for (int o = 16; o; o >>= 1) var += __shfl_xor_sync(0xffffffffu, var, o);
        float rstd = rsqrtf(var * (1.0f/Hd) + 1e-5f);
        #pragma unroll
        for (int i = 0; i < 4; i++) {
            int cc = lane + 32*i;
            tile[l][cc] = (v[i]-mu)*rstd*nw[cc] + nb[cc];
        }
    }
    __syncthreads();
    for (int idx = tid; idx < 32*Hd; idx += 256) {
        int hh = idx >> 5, l = idx & 31;
        g_hnT[((size_t)(b*Hd + hh))*Lseq + l0 + l] = tile[l][hh];
    }
}

// ---------------- FUSED cauchy + kernel-spectrum, batched over layers ----------------
__global__ __launch_bounds__(512) void ckfft_kernel(
        const float* __restrict__ lre, const float* __restrict__ lim,
        const float* __restrict__ pre, const float* __restrict__ pim,
        const float* __restrict__ bre, const float* __restrict__ bim,
        const float* __restrict__ cre, const float* __restrict__ cim,
        const float* __restrict__ lstep) {
    extern __shared__ float2 sm[];
    float2* A  = sm;           // 2048
    float2* Bb = sm + Lseq;    // 2048
    __shared__ float2 slam[Nst];
    __shared__ ull sp[4][Nst][2];
    int h = blockIdx.x, lay = blockIdx.y;
    int hh = lay*Hd + h;
    int tid = threadIdx.x;
    if (tid < Nst) {
        int idx = hh*Nst + tid;
        slam[tid] = make_float2(lre[idx], lim[idx]);
        float2 P  = make_float2(pre[idx], pim[idx]);
        float2 Bv = make_float2(bre[idx], bim[idx]);
        float2 Cc = make_float2(cre[idx], -cim[idx]);
        float2 Pc = make_float2(P.x, -P.y);
        float2 vm[4];
        vm[0] = cmulf(Cc, Bv); vm[1] = cmulf(Cc, P);
        vm[2] = cmulf(Pc, Bv); vm[3] = cmulf(Pc, P);
        #pragma unroll
        for (int m = 0; m < 4; m++) {
            sp[m][tid][0] = pk(vm[m].x, vm[m].y);
            sp[m][tid][1] = pk(vm[m].y, -vm[m].x);
        }
    }
    __syncthreads();
    float ts = 2.0f / __expf(lstep[hh]);
    for (int l = tid; l < Lseq; l += 512) {
        // XLA-style omega (f32 angle + sincosf; l=L/2 must NOT be exactly -1)
        float ang = -6.2831853071795864f * ((float)l / (float)Lseq);
        float s, c;
        sincosf(ang, &s, &c);
        float dpx = 1.0f + c, dpy = s;
        float dmx = 1.0f - c, dmy = -s;
        float id2 = __fdividef(1.0f, dpx*dpx + dpy*dpy);
        float gx = ts * (dmx*dpx + dmy*dpy) * id2;
        float gy = ts * (dmy*dpx - dmx*dpy) * id2;
        float c2x = 2.0f*dpx*id2, c2y = -2.0f*dpy*id2;
        ull acc[4] = {0ull, 0ull, 0ull, 0ull};
        #pragma unroll 8
        for (int n = 0; n < Nst; n++) {
            float dx = gx - slam[n].x;
            float dy = gy - slam[n].y;
            float inv = __fdividef(1.0f, dx*dx + dy*dy);
            float rx = dx*inv, ryp = dy*inv;
            ull rxx = pk(rx, rx), ryy = pk(ryp, ryp);
            #pragma unroll
            for (int m = 0; m < 4; m++)
                acc[m] = ffma2(sp[m][n][0], rxx, ffma2(sp[m][n][1], ryy, acc[m]));
        }
        float k00x,k00y,k01x,k01y,k10x,k10y,k11x,k11y;
        upk(acc[0], k00x, k00y); upk(acc[1], k01x, k01y);
        upk(acc[2], k10x, k10y); upk(acc[3], k11x, k11y);
        float opx = 1.0f + k11x, opy = k11y;
        float oinv = __fdividef(1.0f, opx*opx + opy*opy);
        float wx = k01x*k10x - k01y*k10y;
        float wy = k01x*k10y + k01y*k10x;
        float cx = (wx*opx + wy*opy) * oinv;
        float cy = (wy*opx - wx*opy) * oinv;
        float rx2 = k00x - cx, ry2 = k00y - cy;
        A[l] = make_float2(c2x*rx2 - c2y*ry2, c2x*ry2 + c2y*rx2);
    }
    __syncthreads();
    float2* Kd = g_Kd + (size_t)hh*L2;
    for (int m = tid; m < Lseq; m += 512) {
        float2 am = A[m];
        float2 ar = A[(Lseq - m) & (Lseq-1)];
        Kd[2*m] = make_float2(0.5f*(am.x + ar.x), 0.5f*(am.y - ar.y));
    }
    float2* r = fft2048_m(A, Bb, true);
    for (int m = tid; m < Lseq; m += 512) {
        float xr = r[m].x * (1.0f/Lseq);
        float2 w = g_tw[m];
        Bb[m] = make_float2(xr * w.x, xr * w.y);
    }
    float2* r2 = fft2048_m(Bb, A, false);
    for (int m = tid; m < Lseq; m += 512)
        Kd[2*m + 1] = r2[m];
}

// ---------------- gated MLP + residual + fused next-layer LN ----------------
__global__ __launch_bounds__(256) void mlp_kernel(const float* __restrict__ b1,
                                                  const float* __restrict__ b2,
                                                  const float* __restrict__ nw,
                                                  const float* __restrict__ nb,
                                                  int lay, int do_ln) {
    const float* __restrict__ w1T = g_w1T + lay*Hd*Hd;
    const float* __restrict__ w2T = g_w2T + lay*Hd*Hd;
    __shared__ ull zs2[Hd][16];
    __shared__ float tile[32][129];
    int row0 = blockIdx.x * 32;
    int b = row0 >> 11, l0 = row0 & 2047;
    int tid = threadIdx.x;
    int c = tid & 127, half = tid >> 7;
    for (int idx = tid; idx < Hd*16; idx += 256) {
        int k = idx >> 4, p = idx & 15;
        float2 v = *(const float2*)&g_yT[((size_t)(b*Hd + k))*Lseq + l0 + 2*p];
        zs2[k][p] = pk(v.x, v.y);
    }
    __syncthreads();
    int p0 = half * 8;
    ull acc1[8], acc2[8];
    {
        float b1v = b1[c], b2v = b2[c];
        ull p1 = pk(b1v, b1v), p2 = pk(b2v, b2v);
        #pragma unroll
        for (int p = 0; p < 8; p++) { acc1[p] = p1; acc2[p] = p2; }
    }
    #pragma unroll 2
    for (int k = 0; k < Hd; k++) {
        float w1v = w1T[k*Hd + c];
        float w2v = w2T[k*Hd + c];
        ull w1p = pk(w1v, w1v), w2p = pk(w2v, w2v);
        #pragma unroll
        for (int p = 0; p < 8; p++) {
            ull zp = zs2[k][p0 + p];
            acc1[p] = ffma2(zp, w1p, acc1[p]);
            acc2[p] = ffma2(zp, w2p, acc2[p]);
        }
    }
    #pragma unroll
    for (int p = 0; p < 8; p++) {
        float o0, o1, g0, g1;
        upk(acc1[p], o0, o1);
        upk(acc2[p], g0, g1);
        int ra = 2*(p0 + p), rb = ra + 1;
        size_t ia = (size_t)(row0 + ra)*Hd + c;
        size_t ib = (size_t)(row0 + rb)*Hd + c;
        float ha = g_h[ia] + o0 / (1.0f + __expf(-g0));
        float hb = g_h[ib] + o1 / (1.0f + __expf(-g1));
        g_h[ia] = ha; g_h[ib] = hb;
        tile[ra][c] = ha; tile[rb][c] = hb;
    }
    if (do_ln) {
        __syncthreads();
        int warp = tid >> 5, lane = tid & 31;
        #pragma unroll
        for (int rr = 0; rr < 4; rr++) {
            int l = warp*4 + rr;
            float v[4]; float sum = 0.f;
            #pragma unroll
            for (int i = 0; i < 4; i++) { v[i] = tile[l][lane + 32*i]; sum += v[i]; }
            #pragma unroll
            for (int o = 16; o; o >>= 1) sum += __shfl_xor_sync(0xffffffffu, sum, o);
            float mu = sum * (1.0f/Hd);
            float var = 0.f;
            #pragma unroll
            for (int i = 0; i < 4; i++) { float t = v[i]-mu; var += t*t; }
            #pragma unroll
            for (int o = 16; o; o >>= 1) var += __shfl_xor_sync(0xffffffffu, var, o);
            float rstd = rsqrtf(var * (1.0f/Hd) + 1e-5f);
            #pragma unroll
            for (int i = 0; i < 4; i++) {
                int cc = lane + 32*i;
                tile[l][cc] = (v[i]-mu)*rstd*nw[cc] + nb[cc];
            }
        }
        __syncthreads();
        for (int idx = tid; idx < 32*Hd; idx += 256) {
            int hh = idx >> 5, l = idx & 31;
            g_hnT[((size_t)(b*Hd + hh))*Lseq + l0 + l] = tile[l][hh];
        }
    }
}

// ---------------- decoder (transposed weights, f32x2 row-pairs) ----------------
__global__ __launch_bounds__(256) void dec_kernel(const float* __restrict__ bias,
                                                  float* __restrict__ out) {
    __shared__ ull zs2[Hd][17];   // (h[2p], h[2p+1]) per channel k; pad 17
    int row0 = blockIdx.x * 32;
    int tid = threadIdx.x;
    for (int idx = tid; idx < Hd*16; idx += 256) {
        int p = idx >> 7, k = idx & 127;
        float v0 = g_h[(size_t)(row0 + 2*p)*Hd + k];
        float v1 = g_h[(size_t)(row0 + 2*p + 1)*Hd + k];
        zs2[k][p] = pk(v0, v1);
    }
    __syncthreads();
    int o = tid & 63, grp = tid >> 6;   // 4 groups x 4 pairs
    ull acc[4];
    {
        float bv = bias[o];
        ull bp = pk(bv, bv);
        #pragma unroll
        for (int p = 0; p < 4; p++) acc[p] = bp;
    }
    #pragma unroll 4
    for (int k = 0; k < Hd; k++) {
        float wv = g_decWT[k*OUTF + o];
        ull wp = pk(wv, wv);
        #pragma unroll
        for (int p = 0; p < 4; p++) acc[p] = ffma2(zs2[k][grp*4 + p], wp, acc[p]);
    }
    #pragma unroll
    for (int p = 0; p < 4; p++) {
        float y0, y1;
        upk(acc[p], y0, y1);
        int pr = grp*4 + p;
        out[(size_t)(row0 + 2*pr)*OUTF + o]     = y0;
        out[(size_t)(row0 + 2*pr + 1)*OUTF + o] = y1;
    }
}

// ---------------- launch ----------------
extern "C" void kernel_launch(void* const* d_in, const int* in_sizes, int n_in,
                              void* d_out, int out_size) {
    const float* x       = (const float*)d_in[0];
    const float* enc_w   = (const float*)d_in[2];
    const float* enc_b   = (const float*)d_in[3];
    const float* dec_w   = (const float*)d_in[4];
    const float* dec_b   = (const float*)d_in[5];
    const float* lam_re  = (const float*)d_in[6];
    const float* lam_im  = (const float*)d_in[7];
    const float* p_re    = (const float*)d_in[8];
    const float* p_im    = (const float*)d_in[9];
    const float* b_re    = (const float*)d_in[10];
    const float* b_im    = (const float*)d_in[11];
    const float* c_re    = (const float*)d_in[12];
    const float* c_im    = (const float*)d_in[13];
    const float* dvec    = (const float*)d_in[14];
    const float* logstep = (const float*)d_in[15];
    const float* norm_w  = (const float*)d_in[16];
    const float* norm_b  = (const float*)d_in[17];
    const float* w1      = (const float*)d_in[18];
    const float* b1      = (const float*)d_in[19];
    const float* w2      = (const float*)d_in[20];
    const float* b2      = (const float*)d_in[21];
    float* out = (float*)d_out;

    int smem_ckfft = 2 * Lseq * (int)sizeof(float2);  // 32 KB (dynamic)
    cudaFuncSetAttribute(ckfft_kernel, cudaFuncAttributeMaxDynamicSharedMemorySize, smem_ckfft);

    twiddle_kernel<<<8, 256>>>();
    prep_kernel<<<(NLAY*Hd*Hd + 255)/256, 256>>>(enc_w, dec_w, w1, w2);
    // all 4 layers' kernel spectra upfront (input-independent)
    ckfft_kernel<<<dim3(Hd, NLAY), 512, smem_ckfft>>>(lam_re, lam_im, p_re, p_im,
                                                      b_re, b_im, c_re, c_im, logstep);
    encoder_kernel<<<ROWS/32, 256>>>(x, enc_b, norm_w, norm_b);  // GEMM + layer-0 LN
    for (int i = 0; i < NLAY; i++) {
        conv_kernel<<<Bsz*Hd/2, 256>>>(dvec + i*Hd, i);
        int last = (i == NLAY-1);
        mlp_kernel<<<ROWS/32, 256>>>(b1 + i*Hd, b2 + i*Hd,
                                     norm_w + (last ? 0 : (i+1)*Hd),
                                     norm_b + (last ? 0 : (i+1)*Hd),
                                     i, last ? 0 : 1);
    }
    dec_kernel<<<ROWS/32, 256>>>(dec_b, out);
}

// round 12
// speedup vs baseline: 4.0254x; 1.0053x over previous
#include <cuda_runtime.h>
#include <math.h>

#define Bsz 8
#define Lseq 2048
#define INF 64
#define OUTF 64
#define Hd 128
#define Nst 64
#define NLAY 4
#define L2 4096
#define ROWS (Bsz*Lseq)

typedef unsigned long long ull;

// ---------------- persistent scratch ----------------
__device__ float  g_h  [ROWS*Hd];          // activations (B,L,H)
__device__ float  g_hnT[Bsz*Hd*Lseq];      // layernormed, transposed (B,H,L)
__device__ float  g_yT [Bsz*Hd*Lseq];      // gelu(conv output), transposed (B,H,L)
__device__ float4 g_KdP[NLAY*(Hd/2)*Lseq]; // spectra f<2048, channel pairs interleaved (K1,K2)
__device__ float2 g_KdN[NLAY*Hd];          // spectrum bin 2048 per channel
__device__ float2 g_tw [L2/2];             // twiddles W_4096^m, m < 2048
__device__ float  g_w1T[NLAY*Hd*Hd];       // transposed weights [k][c]
__device__ float  g_w2T[NLAY*Hd*Hd];
__device__ float  g_encWT[INF*Hd];
__device__ float  g_decWT[Hd*OUTF];

__device__ __forceinline__ float2 cmulf(float2 a, float2 b) {
    return make_float2(a.x*b.x - a.y*b.y, a.x*b.y + a.y*b.x);
}
__device__ __forceinline__ float2 caddf(float2 a, float2 b){ return make_float2(a.x+b.x, a.y+b.y); }
__device__ __forceinline__ float2 csubf(float2 a, float2 b){ return make_float2(a.x-b.x, a.y-b.y); }
// a + sgn*i*d
__device__ __forceinline__ float2 addi(float2 a, float2 d, float sgn) {
    return make_float2(a.x - sgn*d.y, a.y + sgn*d.x);
}
// ---- packed f32x2 helpers ----
__device__ __forceinline__ ull pk(float x, float y) {
    ull r; asm("mov.b64 %0, {%1, %2};" : "=l"(r) : "f"(x), "f"(y)); return r;
}
__device__ __forceinline__ void upk(ull p, float& x, float& y) {
    asm("mov.b64 {%0, %1}, %2;" : "=f"(x), "=f"(y) : "l"(p));
}
__device__ __forceinline__ ull ffma2(ull a, ull b, ull c) {
    ull d; asm("fma.rn.f32x2 %0, %1, %2, %3;" : "=l"(d) : "l"(a), "l"(b), "l"(c)); return d;
}

// ---------------- prep: twiddles + weight transposes (one launch) ----------------
__global__ void prep_kernel(const float* __restrict__ enc_w, const float* __restrict__ dec_w,
                            const float* __restrict__ w1, const float* __restrict__ w2) {
    int tid = blockIdx.x * 256 + threadIdx.x;
    if (tid < L2/2) {
        float s, c;
        sincospif(-(float)tid / 2048.0f, &s, &c);
        g_tw[tid] = make_float2(c, s);
    }
    if (tid < INF*Hd) { int k = tid >> 7, c = tid & 127; g_encWT[tid] = enc_w[c*INF + k]; }
    if (tid < Hd*OUTF) { int k = tid >> 6, o = tid & 63; g_decWT[tid] = dec_w[o*Hd + k]; }
    if (tid < NLAY*Hd*Hd) {
        int lay = tid >> 14, r = tid & 16383, k = r >> 7, c = r & 127;
        g_w1T[tid] = w1[lay*Hd*Hd + c*Hd + k];
        g_w2T[tid] = w2[lay*Hd*Hd + c*Hd + k];
    }
}

// ---------------- radix-8 butterfly (DIT-style: twiddles applied to inputs) ----------------
__device__ __forceinline__ void radix8(const float2 u[8],
                                       float2 w1, float2 w2, float2 w3, float2 w4,
                                       float sgnF, float2 out[8]) {
    const float cc = 0.70710678118654752f;
    float2 w5 = cmulf(w4, w1);
    float2 w6 = cmulf(w3, w3);
    float2 w7 = cmulf(w4, w3);
    float2 t0 = u[0];
    float2 t1 = cmulf(w1, u[1]);
    float2 t2 = cmulf(w2, u[2]);
    float2 t3 = cmulf(w3, u[3]);
    float2 t4 = cmulf(w4, u[4]);
    float2 t5 = cmulf(w5, u[5]);
    float2 t6 = cmulf(w6, u[6]);
    float2 t7 = cmulf(w7, u[7]);
    float2 s04 = caddf(t0, t4), d04 = csubf(t0, t4);
    float2 s26 = caddf(t2, t6), d26 = csubf(t2, t6);
    float2 s15 = caddf(t1, t5), d15 = csubf(t1, t5);
    float2 s37 = caddf(t3, t7), d37 = csubf(t3, t7);
    float2 E0 = caddf(s04, s26), E2 = csubf(s04, s26);
    float2 E1 = addi(d04, d26, sgnF), E3 = addi(d04, d26, -sgnF);
    float2 O0 = caddf(s15, s37), O2 = csubf(s15, s37);
    float2 O1 = addi(d15, d37, sgnF), O3 = addi(d15, d37, -sgnF);
    float2 W81 = make_float2(cc,  sgnF*cc);
    float2 W83 = make_float2(-cc, sgnF*cc);
    float2 p1 = cmulf(O1, W81);
    float2 p2 = make_float2(-sgnF*O2.y, sgnF*O2.x);   // sgnF * i * O2
    float2 p3 = cmulf(O3, W83);
    out[0] = caddf(E0, O0); out[4] = csubf(E0, O0);
    out[1] = caddf(E1, p1); out[5] = csubf(E1, p1);
    out[2] = caddf(E2, p2); out[6] = csubf(E2, p2);
    out[3] = caddf(E3, p3); out[7] = csubf(E3, p3);
}

// ---------------- 2048-pt Stockham FFT: radix-4 then 3x radix-8 (result in `a`) ----------------
__device__ float2* fft2048_m(float2* a, float2* b, bool inverse) {
    float2* src = a; float2* dst = b;
    const float sgnF = inverse ? 1.0f : -1.0f;
    __syncthreads();
    for (int j = threadIdx.x; j < 512; j += blockDim.x) {
        float2 u0 = src[j], u1 = src[j+512], u2 = src[j+1024], u3 = src[j+1536];
        float2 a02 = caddf(u0, u2), s02 = csubf(u0, u2);
        float2 a13 = caddf(u1, u3), s13 = csubf(u1, u3);
        int o = j << 2;
        dst[o  ] = caddf(a02, a13);
        dst[o+1] = addi(s02, s13, sgnF);
        dst[o+2] = csubf(a02, a13);
        dst[o+3] = addi(s02, s13, -sgnF);
    }
    { float2* tmp = src; src = dst; dst = tmp; }
    int L = 4, mult = 128;
    #pragma unroll
    for (int t = 0; t < 3; t++) {
        __syncthreads();
        for (int j = threadIdx.x; j < 256; j += blockDim.x) {
            int k = j & (L - 1);
            int blk = j >> (2 + 3*t);
            float2 u[8];
            #pragma unroll
            for (int i = 0; i < 8; i++) u[i] = src[j + i*256];
            int idx = k * mult;
            float2 w1 = g_tw[idx], w2 = g_tw[2*idx], w3 = g_tw[3*idx], w4 = g_tw[4*idx];
            if (inverse) { w1.y = -w1.y; w2.y = -w2.y; w3.y = -w3.y; w4.y = -w4.y; }
            float2 o8[8];
            radix8(u, w1, w2, w3, w4, sgnF, o8);
            int o = (blk << 3)*L + k;
            #pragma unroll
            for (int i = 0; i < 8; i++) dst[o + i*L] = o8[i];
        }
        { float2* tmp = src; src = dst; dst = tmp; }
        L <<= 3; mult >>= 3;
    }
    __syncthreads();
    return src;
}

// ---------------- one in-place radix-8 stage (4096 pts, 256 threads, 2 bf/thread) ----------------
__device__ __forceinline__ void stage_ip(float2* A, int t, int L, int mult,
                                         float sgnF, bool conj) {
    float2 u[2][8];
    #pragma unroll
    for (int q = 0; q < 2; q++) {
        int j = threadIdx.x + q*256;
        #pragma unroll
        for (int i = 0; i < 8; i++) u[q][i] = A[j + i*512];
    }
    __syncthreads();
    #pragma unroll
    for (int q = 0; q < 2; q++) {
        int j = threadIdx.x + q*256;
        int k = j & (L - 1);
        int blkq = j >> (3*t);
        int idx = k * mult;
        float2 w1 = g_tw[idx], w2 = g_tw[2*idx], w3 = g_tw[3*idx], w4 = g_tw[4*idx];
        if (conj) { w1.y = -w1.y; w2.y = -w2.y; w3.y = -w3.y; w4.y = -w4.y; }
        float2 o8[8];
        radix8(u[q], w1, w2, w3, w4, sgnF, o8);
        int o = (blkq << (3*t + 3)) + k;
        #pragma unroll
        for (int i = 0; i < 8; i++) A[o + i*L] = o8[i];
    }
    __syncthreads();
}

// ---------------- FFT causal conv, in-place single-buffer (32 KB), real-kernel symmetry ----------------
__global__ __launch_bounds__(256, 4) void conv_kernel(const float* __restrict__ dvec, int lay) {
    __shared__ float2 A[L2];
    int blk = blockIdx.x;
    int b = blk >> 6, hp = blk & 63;
    int h0 = 2*hp;
    int tid = threadIdx.x;
    const float* u1 = g_hnT + ((size_t)b*Hd + h0)*Lseq;
    const float* u2 = u1 + Lseq;
    const float2 ONE = make_float2(1.f, 0.f);

    // forward stage 0 (L=1, twiddles=1): global -> butterflies -> A; upper half is zero
    #pragma unroll
    for (int q = 0; q < 2; q++) {
        int j = tid + q*256;
        float2 u[8], o8[8];
        #pragma unroll
        for (int i = 0; i < 4; i++) u[i] = make_float2(u1[j + i*512], u2[j + i*512]);
        #pragma unroll
        for (int i = 4; i < 8; i++) u[i] = make_float2(0.f, 0.f);
        radix8(u, ONE, ONE, ONE, ONE, -1.0f, o8);
        #pragma unroll
        for (int i = 0; i < 8; i++) A[(j << 3) + i] = o8[i];
    }
    __syncthreads();
    // forward stages 1..3
    stage_ip(A, 1, 8,   64, -1.0f, false);
    stage_ip(A, 2, 64,  8,  -1.0f, false);
    stage_ip(A, 3, 512, 1,  -1.0f, false);

    // pointwise using K-real symmetry: compute Y at f<2048 once, emit f and 4096-f.
    const float4* KP = g_KdP + ((size_t)lay*(Hd/2) + hp)*Lseq;
    #pragma unroll
    for (int s = 0; s < 8; s++) {
        int f  = tid + s*256;              // 0..2047
        int fr = (L2 - f) & (L2-1);
        float2 zf = A[f], zr = A[fr];
        float4 K = KP[f];
        float2 K1 = make_float2(K.x, K.y), K2 = make_float2(K.z, K.w);
        float2 U1 = make_float2(0.5f*(zf.x + zr.x),  0.5f*(zf.y - zr.y));
        float2 U2 = make_float2(0.5f*(zf.y + zr.y), -0.5f*(zf.x - zr.x));
        float2 Y1 = cmulf(U1, K1);
        float2 Y2 = cmulf(U2, K2);
        A[f] = make_float2(Y1.x - Y2.y, Y1.y + Y2.x);
        if (f != 0)
            A[fr] = make_float2(Y1.x + Y2.y, Y2.x - Y1.y);   // conj(Y1) + i*conj(Y2)
        if (f == 0) {   // self-paired Nyquist bin 2048
            float2 z = A[2048];
            float2 K1n = g_KdN[lay*Hd + h0];
            float2 K2n = g_KdN[lay*Hd + h0 + 1];
            float2 Y1n = make_float2(z.x*K1n.x, z.x*K1n.y);
            float2 Y2n = make_float2(z.y*K2n.x, z.y*K2n.y);
            A[2048] = make_float2(Y1n.x - Y2n.y, Y1n.y + Y2n.x);
        }
    }
    __syncthreads();

    // inverse stage 0 (L=1, twiddles=1)
    {
        float2 u[2][8];
        #pragma unroll
        for (int q = 0; q < 2; q++) {
            int j = tid + q*256;
            #pragma unroll
            for (int i = 0; i < 8; i++) u[q][i] = A[j + i*512];
        }
        __syncthreads();
        #pragma unroll
        for (int q = 0; q < 2; q++) {
            int j = tid + q*256;
            float2 o8[8];
            radix8(u[q], ONE, ONE, ONE, ONE, 1.0f, o8);
            #pragma unroll
            for (int i = 0; i < 8; i++) A[(j << 3) + i] = o8[i];
        }
        __syncthreads();
    }
    stage_ip(A, 1, 8,  64, 1.0f, true);
    stage_ip(A, 2, 64, 8,  1.0f, true);
    // inverse stage 3 fused with epilogue: keep only l < 2048 (i < 4), write global
    {
        float d1 = dvec[h0], d2 = dvec[h0+1];
        float* y1 = g_yT + ((size_t)b*Hd + h0)*Lseq;
        float* y2 = y1 + Lseq;
        float2 u[2][8];
        #pragma unroll
        for (int q = 0; q < 2; q++) {
            int j = tid + q*256;
            #pragma unroll
            for (int i = 0; i < 8; i++) u[q][i] = A[j + i*512];
        }
        // no smem writes follow -> no barrier needed
        #pragma unroll
        for (int q = 0; q < 2; q++) {
            int j = tid + q*256;          // k = j (L=512), blk = 0
            int idx = j;                   // mult = 1
            float2 w1 = g_tw[idx], w2 = g_tw[2*idx], w3 = g_tw[3*idx], w4 = g_tw[4*idx];
            w1.y = -w1.y; w2.y = -w2.y; w3.y = -w3.y; w4.y = -w4.y;
            float2 o8[8];
            radix8(u[q], w1, w2, w3, w4, 1.0f, o8);
            #pragma unroll
            for (int i = 0; i < 4; i++) {
                int l = j + i*512;
                float v1 = o8[i].x*(1.0f/L2) + u1[l]*d1;
                float v2 = o8[i].y*(1.0f/L2) + u2[l]*d2;
                float t1 = 0.7978845608028654f * (v1 + 0.044715f * v1*v1*v1);
                float t2 = 0.7978845608028654f * (v2 + 0.044715f * v2*v2*v2);
                y1[l] = 0.5f * v1 * (1.0f + tanhf(t1));
                y2[l] = 0.5f * v2 * (1.0f + tanhf(t2));
            }
        }
    }
}

// ---------------- encoder GEMM (f32x2 row-pairs) + fused layer-0 LN -> g_h, g_hnT ----------------
__global__ __launch_bounds__(256) void encoder_kernel(const float* __restrict__ x,
                                                      const float* __restrict__ eb,
                                                      const float* __restrict__ nw,
                                                      const float* __restrict__ nb) {
    __shared__ float xs[32][INF];     // staged input rows
    __shared__ ull   zs2[INF][17];    // packed row-pairs (pad 17 to break bank conflicts)
    __shared__ float tile[32][129];   // h rows for LN
    int row0 = blockIdx.x * 32;
    int b = row0 >> 11, l0 = row0 & 2047;
    int tid = threadIdx.x;
    for (int idx = tid; idx < 32*INF; idx += 256)
        xs[idx >> 6][idx & 63] = x[(size_t)(row0 + (idx >> 6))*INF + (idx & 63)];
    __syncthreads();
    for (int idx = tid; idx < INF*16; idx += 256) {
        int p = idx >> 6, k = idx & 63;
        zs2[k][p] = pk(xs[2*p][k], xs[2*p+1][k]);
    }
    __syncthreads();
    int c = tid & 127, half = tid >> 7;
    int p0 = half * 8;
    ull acc[8];
    {
        float bv = eb[c];
        ull bp = pk(bv, bv);
        #pragma unroll
        for (int p = 0; p < 8; p++) acc[p] = bp;
    }
    #pragma unroll 4
    for (int k = 0; k < INF; k++) {
        float wv = g_encWT[k*Hd + c];
        ull wp = pk(wv, wv);
        #pragma unroll
        for (int p = 0; p < 8; p++) acc[p] = ffma2(zs2[k][p0 + p], wp, acc[p]);
    }
    #pragma unroll
    for (int p = 0; p < 8; p++) {
        float h0v, h1v;
        upk(acc[p], h0v, h1v);
        int ra = 2*(p0 + p), rb = ra + 1;
        g_h[(size_t)(row0 + ra)*Hd + c] = h0v;
        g_h[(size_t)(row0 + rb)*Hd + c] = h1v;
        tile[ra][c] = h0v; tile[rb][c] = h1v;
    }
    __syncthreads();
    int warp = tid >> 5, lane = tid & 31;
    #pragma unroll
    for (int rr = 0; rr < 4; rr++) {
        int l = warp*4 + rr;
        float v[4]; float sum = 0.f;
        #pragma unroll
        for (int i = 0; i < 4; i++) { v[i] = tile[l][lane + 32*i]; sum += v[i]; }
        #pragma unroll
        for (int o = 16; o; o >>= 1) sum += __shfl_xor_sync(0xffffffffu, sum, o);
        float mu = sum * (1.0f/Hd);
        float var = 0.f;
        #pragma unroll
        for (int i = 0; i < 4; i++) { float t = v[i]-mu; var += t*t; }
        #pragma unroll
        for (int o = 16; o; o >>= 1) var += __shfl_xor_sync(0xffffffffu, var, o);
        float rstd = rsqrtf(var * (1.0f/Hd) + 1e-5f);
        #pragma unroll
        for (int i = 0; i < 4; i++) {
            int cc = lane + 32*i;
            tile[l][cc] = (v[i]-mu)*rstd*nw[cc] + nb[cc];
        }
    }
    __syncthreads();
    for (int idx = tid; idx < 32*Hd; idx += 256) {
        int hh = idx >> 5, l = idx & 31;
        g_hnT[((size_t)(b*Hd + hh))*Lseq + l0 + l] = tile[l][hh];
    }
}

// ---------------- FUSED cauchy + kernel-spectrum (symmetric storage), batched over layers ----------------
__global__ __launch_bounds__(512) void ckfft_kernel(
        const float* __restrict__ lre, const float* __restrict__ lim,
        const float* __restrict__ pre, const float* __restrict__ pim,
        const float* __restrict__ bre, const float* __restrict__ bim,
        const float* __restrict__ cre, const float* __restrict__ cim,
        const float* __restrict__ lstep) {
    extern __shared__ float2 sm[];
    float2* A  = sm;           // 2048
    float2* Bb = sm + Lseq;    // 2048
    __shared__ float2 slam[Nst];
    __shared__ ull sp[4][Nst][2];
    int h = blockIdx.x, lay = blockIdx.y;
    int hh = lay*Hd + h;
    int tid = threadIdx.x;
    if (tid < Nst) {
        int idx = hh*Nst + tid;
        slam[tid] = make_float2(lre[idx], lim[idx]);
        float2 P  = make_float2(pre[idx], pim[idx]);
        float2 Bv = make_float2(bre[idx], bim[idx]);
        float2 Cc = make_float2(cre[idx], -cim[idx]);
        float2 Pc = make_float2(P.x, -P.y);
        float2 vm[4];
        vm[0] = cmulf(Cc, Bv); vm[1] = cmulf(Cc, P);
        vm[2] = cmulf(Pc, Bv); vm[3] = cmulf(Pc, P);
        #pragma unroll
        for (int m = 0; m < 4; m++) {
            sp[m][tid][0] = pk(vm[m].x, vm[m].y);
            sp[m][tid][1] = pk(vm[m].y, -vm[m].x);
        }
    }
    __syncthreads();
    float ts = 2.0f / __expf(lstep[hh]);
    for (int l = tid; l < Lseq; l += 512) {
        // XLA-style omega (f32 angle + sincosf; l=L/2 must NOT be exactly -1)
        float ang = -6.2831853071795864f * ((float)l / (float)Lseq);
        float s, c;
        sincosf(ang, &s, &c);
        float dpx = 1.0f + c, dpy = s;
        float dmx = 1.0f - c, dmy = -s;
        float id2 = __fdividef(1.0f, dpx*dpx + dpy*dpy);
        float gx = ts * (dmx*dpx + dmy*dpy) * id2;
        float gy = ts * (dmy*dpx - dmx*dpy) * id2;
        float c2x = 2.0f*dpx*id2, c2y = -2.0f*dpy*id2;
        ull acc[4] = {0ull, 0ull, 0ull, 0ull};
        #pragma unroll 8
        for (int n = 0; n < Nst; n++) {
            float dx = gx - slam[n].x;
            float dy = gy - slam[n].y;
            float inv = __fdividef(1.0f, dx*dx + dy*dy);
            float rx = dx*inv, ryp = dy*inv;
            ull rxx = pk(rx, rx), ryy = pk(ryp, ryp);
            #pragma unroll
            for (int m = 0; m < 4; m++)
                acc[m] = ffma2(sp[m][n][0], rxx, ffma2(sp[m][n][1], ryy, acc[m]));
        }
        float k00x,k00y,k01x,k01y,k10x,k10y,k11x,k11y;
        upk(acc[0], k00x, k00y); upk(acc[1], k01x, k01y);
        upk(acc[2], k10x, k10y); upk(acc[3], k11x, k11y);
        float opx = 1.0f + k11x, opy = k11y;
        float oinv = __fdividef(1.0f, opx*opx + opy*opy);
        float wx = k01x*k10x - k01y*k10y;
        float wy = k01x*k10y + k01y*k10x;
        float cx = (wx*opx + wy*opy) * oinv;
        float cy = (wy*opx - wx*opy) * oinv;
        float rx2 = k00x - cx, ry2 = k00y - cy;
        A[l] = make_float2(c2x*rx2 - c2y*ry2, c2x*ry2 + c2y*rx2);
    }
    __syncthreads();
    // Kd storage: pair-interleaved float4 (slot h&1), f<2048 only; bin 2048 separate.
    float2* KP2 = (float2*)(g_KdP + ((size_t)lay*(Hd/2) + (h>>1))*Lseq);  // index 2*f + slot
    int slot = h & 1;
    // even bins from at (A) BEFORE the in-place IFFT destroys it
    for (int m = tid; m < Lseq; m += 512) {
        if (m < 1024) {
            float2 am = A[m];
            float2 ar = A[(Lseq - m) & (Lseq-1)];
            KP2[4*m + slot] = make_float2(0.5f*(am.x + ar.x), 0.5f*(am.y - ar.y));  // f=2m
        } else if (m == 1024) {
            g_KdN[hh] = make_float2(A[1024].x, 0.f);   // bin 2048
        }
    }
    float2* r = fft2048_m(A, Bb, true);
    for (int m = tid; m < Lseq; m += 512) {
        float xr = r[m].x * (1.0f/Lseq);
        float2 w = g_tw[m];
        Bb[m] = make_float2(xr * w.x, xr * w.y);
    }
    float2* r2 = fft2048_m(Bb, A, false);
    for (int m = tid; m < 1024; m += 512)
        KP2[4*m + 2 + slot] = r2[m];                   // f=2m+1
}

// ---------------- gated MLP + residual + fused next-layer LN (64 rows, 512 threads) ----------------
__global__ __launch_bounds__(512) void mlp_kernel(const float* __restrict__ b1,
                                                  const float* __restrict__ b2,
                                                  const float* __restrict__ nw,
                                                  const float* __restrict__ nb,
                                                  int lay, int do_ln) {
    const float* __restrict__ w1T = g_w1T + lay*Hd*Hd;
    const float* __restrict__ w2T = g_w2T + lay*Hd*Hd;
    // union: zs2 (32 KB, GEMM phase) then tile (33 KB, LN phase)
    __shared__ __align__(16) unsigned char smbuf[64*129*4];
    ull   (*zs2)[32]  = reinterpret_cast<ull(*)[32]>(smbuf);
    float (*tile)[129] = reinterpret_cast<float(*)[129]>(smbuf);
    int row0 = blockIdx.x * 64;
    int b = row0 >> 11, l0 = row0 & 2047;
    int tid = threadIdx.x;
    int c = tid & 127, grp = tid >> 7;   // 4 groups
    for (int idx = tid; idx < Hd*32; idx += 512) {
        int k = idx >> 5, p = idx & 31;
        float2 v = *(const float2*)&g_yT[((size_t)(b*Hd + k))*Lseq + l0 + 2*p];
        zs2[k][p] = pk(v.x, v.y);
    }
    __syncthreads();
    int p0 = grp * 8;
    ull acc1[8], acc2[8];
    {
        float b1v = b1[c], b2v = b2[c];
        ull p1 = pk(b1v, b1v), p2 = pk(b2v, b2v);
        #pragma unroll
        for (int p = 0; p < 8; p++) { acc1[p] = p1; acc2[p] = p2; }
    }
    #pragma unroll 2
    for (int k = 0; k < Hd; k++) {
        float w1v = w1T[k*Hd + c];
        float w2v = w2T[k*Hd + c];
        ull w1p = pk(w1v, w1v), w2p = pk(w2v, w2v);
        #pragma unroll
        for (int p = 0; p < 8; p++) {
            ull zp = zs2[k][p0 + p];
            acc1[p] = ffma2(zp, w1p, acc1[p]);
            acc2[p] = ffma2(zp, w2p, acc2[p]);
        }
    }
    __syncthreads();   // zs2 dead; tile may now alias it
    float hva[8], hvb[8];
    #pragma unroll
    for (int p = 0; p < 8; p++) {
        float o0, o1, g0, g1;
        upk(acc1[p], o0, o1);
        upk(acc2[p], g0, g1);
        int ra = 2*(p0 + p), rb = ra + 1;
        size_t ia = (size_t)(row0 + ra)*Hd + c;
        size_t ib = (size_t)(row0 + rb)*Hd + c;
        float ha = g_h[ia] + o0 / (1.0f + __expf(-g0));
        float hb = g_h[ib] + o1 / (1.0f + __expf(-g1));
        g_h[ia] = ha; g_h[ib] = hb;
        hva[p] = ha; hvb[p] = hb;
    }
    if (do_ln) {
        #pragma unroll
        for (int p = 0; p < 8; p++) {
            int ra = 2*(p0 + p);
            tile[ra][c] = hva[p]; tile[ra+1][c] = hvb[p];
        }
        __syncthreads();
        int warp = tid >> 5, lane = tid & 31;
        #pragma unroll
        for (int rr = 0; rr < 4; rr++) {
            int l = warp*4 + rr;   // 16 warps x 4 = 64 rows
            float v[4]; float sum = 0.f;
            #pragma unroll
            for (int i = 0; i < 4; i++) { v[i] = tile[l][lane + 32*i]; sum += v[i]; }
            #pragma unroll
            for (int o = 16; o; o >>= 1) sum += __shfl_xor_sync(0xffffffffu, sum, o);
            float mu = sum * (1.0f/Hd);
            float var = 0.f;
            #pragma unroll
            for (int i = 0; i < 4; i++) { float t = v[i]-mu; var += t*t; }
            #pragma unroll
            for (int o = 16; o; o >>= 1) var += __shfl_xor_sync(0xffffffffu, var, o);
            float rstd = rsqrtf(var * (1.0f/Hd) + 1e-5f);
            #pragma unroll
            for (int i = 0; i < 4; i++) {
                int cc = lane + 32*i;
                tile[l][cc] = (v[i]-mu)*rstd*nw[cc] + nb[cc];
            }
        }
        __syncthreads();
        for (int idx = tid; idx < 64*Hd; idx += 512) {
            int hh = idx >> 6, l = idx & 63;
            g_hnT[((size_t)(b*Hd + hh))*Lseq + l0 + l] = tile[l][hh];
        }
    }
}

// ---------------- decoder (transposed weights, f32x2 row-pairs) ----------------
__global__ __launch_bounds__(256) void dec_kernel(const float* __restrict__ bias,
                                                  float* __restrict__ out) {
    __shared__ ull zs2[Hd][17];   // (h[2p], h[2p+1]) per channel k; pad 17
    int row0 = blockIdx.x * 32;
    int tid = threadIdx.x;
    for (int idx = tid; idx < Hd*16; idx += 256) {
        int p = idx >> 7, k = idx & 127;
        float v0 = g_h[(size_t)(row0 + 2*p)*Hd + k];
        float v1 = g_h[(size_t)(row0 + 2*p + 1)*Hd + k];
        zs2[k][p] = pk(v0, v1);
    }
    __syncthreads();
    int o = tid & 63, grp = tid >> 6;   // 4 groups x 4 pairs
    ull acc[4];
    {
        float bv = bias[o];
        ull bp = pk(bv, bv);
        #pragma unroll
        for (int p = 0; p < 4; p++) acc[p] = bp;
    }
    #pragma unroll 4
    for (int k = 0; k < Hd; k++) {
        float wv = g_decWT[k*OUTF + o];
        ull wp = pk(wv, wv);
        #pragma unroll
        for (int p = 0; p < 4; p++) acc[p] = ffma2(zs2[k][grp*4 + p], wp, acc[p]);
    }
    #pragma unroll
    for (int p = 0; p < 4; p++) {
        float y0, y1;
        upk(acc[p], y0, y1);
        int pr = grp*4 + p;
        out[(size_t)(row0 + 2*pr)*OUTF + o]     = y0;
        out[(size_t)(row0 + 2*pr + 1)*OUTF + o] = y1;
    }
}

// ---------------- launch ----------------
extern "C" void kernel_launch(void* const* d_in, const int* in_sizes, int n_in,
                              void* d_out, int out_size) {
    const float* x       = (const float*)d_in[0];
    const float* enc_w   = (const float*)d_in[2];
    const float* enc_b   = (const float*)d_in[3];
    const float* dec_w   = (const float*)d_in[4];
    const float* dec_b   = (const float*)d_in[5];
    const float* lam_re  = (const float*)d_in[6];
    const float* lam_im  = (const float*)d_in[7];
    const float* p_re    = (const float*)d_in[8];
    const float* p_im    = (const float*)d_in[9];
    const float* b_re    = (const float*)d_in[10];
    const float* b_im    = (const float*)d_in[11];
    const float* c_re    = (const float*)d_in[12];
    const float* c_im    = (const float*)d_in[13];
    const float* dvec    = (const float*)d_in[14];
    const float* logstep = (const float*)d_in[15];
    const float* norm_w  = (const float*)d_in[16];
    const float* norm_b  = (const float*)d_in[17];
    const float* w1      = (const float*)d_in[18];
    const float* b1      = (const float*)d_in[19];
    const float* w2      = (const float*)d_in[20];
    const float* b2      = (const float*)d_in[21];
    float* out = (float*)d_out;

    int smem_ckfft = 2 * Lseq * (int)sizeof(float2);  // 32 KB (dynamic)
    cudaFuncSetAttribute(ckfft_kernel, cudaFuncAttributeMaxDynamicSharedMemorySize, smem_ckfft);

    prep_kernel<<<(NLAY*Hd*Hd + 255)/256, 256>>>(enc_w, dec_w, w1, w2);
    // all 4 layers' kernel spectra upfront (input-independent)
    ckfft_kernel<<<dim3(Hd, NLAY), 512, smem_ckfft>>>(lam_re, lam_im, p_re, p_im,
                                                      b_re, b_im, c_re, c_im, logstep);
    encoder_kernel<<<ROWS/32, 256>>>(x, enc_b, norm_w, norm_b);  // GEMM + layer-0 LN
    for (int i = 0; i < NLAY; i++) {
        conv_kernel<<<Bsz*Hd/2, 256>>>(dvec + i*Hd, i);
        int last = (i == NLAY-1);
        mlp_kernel<<<ROWS/64, 512>>>(b1 + i*Hd, b2 + i*Hd,
                                     norm_w + (last ? 0 : (i+1)*Hd),
                                     norm_b + (last ? 0 : (i+1)*Hd),
                                     i, last ? 0 : 1);
    }
    dec_kernel<<<ROWS/32, 256>>>(dec_b, out);
}